// round 2
// baseline (speedup 1.0000x reference)
#include <cuda_runtime.h>

// ============================================================================
// QuConVXYZ: 20-qubit circuit (RX/RY/RZ layer, RXX/RYY/RZZ chain, RX/RY/RZ
// layer) on batch-4 state, then 10-qubit reduced density matrix.
//
// Key reductions:
//  - RZ*RY*RX per wire  -> one fused 2x2 complex gate
//  - RZZ*RYY*RXX per pair -> two 2x2 complex blocks on (00,11) and (01,10)
//  - whole circuit in 2 smem-tiled passes
//  - RDM = batched complex A^T conj(A) syrk with Hermitian-mirror writes,
//    inner loop on packed fma.rn.f32x2 (Re/Im lanes fused)
// ============================================================================

#define BATCH 4
#define NQ 20
#define DIM (1u << NQ)

__device__ float2 g_state[BATCH * DIM];  // 32 MB scratch

__device__ float2 d_U1[20][4];   // fused layer-1 single-qubit gates (row major 2x2)
__device__ float2 d_U2[20][4];   // fused layer-2 single-qubit gates
__device__ float2 d_G00[19][4];  // chain gate block on (|00>,|11>)
__device__ float2 d_G01[19][4];  // chain gate block on (|01>,|10>)

// ---------------------------------------------------------------------------
// Gate precompute (double precision, trivial cost)
// ---------------------------------------------------------------------------
struct cd { double re, im; };
__device__ __forceinline__ cd cmuld(cd a, cd b) {
    return {a.re * b.re - a.im * b.im, a.re * b.im + a.im * b.re};
}
__device__ __forceinline__ cd caddd(cd a, cd b) { return {a.re + b.re, a.im + b.im}; }
__device__ void mm2(const cd* A, const cd* B, cd* C) {
    C[0] = caddd(cmuld(A[0], B[0]), cmuld(A[1], B[2]));
    C[1] = caddd(cmuld(A[0], B[1]), cmuld(A[1], B[3]));
    C[2] = caddd(cmuld(A[2], B[0]), cmuld(A[3], B[2]));
    C[3] = caddd(cmuld(A[2], B[1]), cmuld(A[3], B[3]));
}

__global__ void kprep(const float* __restrict__ w) {
    int t = threadIdx.x;
    const double WM = 0.6324555320336759;  // sqrt(2)/sqrt(5)
    if (t < 40) {
        int q = t % 20;
        int base = (t < 20) ? 3 * q : (117 + 3 * q);  // layer1 | layer2 params
        double ax = (double)w[base]     * WM * 0.5;
        double ay = (double)w[base + 1] * WM * 0.5;
        double az = (double)w[base + 2] * WM * 0.5;
        double cx = cos(ax), sx = sin(ax);
        double cy = cos(ay), sy = sin(ay);
        double cz = cos(az), sz = sin(az);
        cd RX[4] = {{cx, 0}, {0, -sx}, {0, -sx}, {cx, 0}};
        cd RY[4] = {{cy, 0}, {-sy, 0}, {sy, 0}, {cy, 0}};
        cd RYX[4]; mm2(RY, RX, RYX);
        cd z0 = {cz, -sz}, z1 = {cz, sz};  // RZ = diag(e^{-ia}, e^{+ia})
        cd U[4] = {cmuld(z0, RYX[0]), cmuld(z0, RYX[1]),
                   cmuld(z1, RYX[2]), cmuld(z1, RYX[3])};
        float2 (*dst)[4] = (t < 20) ? d_U1 : d_U2;
        for (int i = 0; i < 4; i++) dst[q][i] = make_float2((float)U[i].re, (float)U[i].im);
    } else if (t < 59) {
        int q = t - 40;
        int base = 60 + 3 * q;
        double ax = (double)w[base]     * WM * 0.5;
        double ay = (double)w[base + 1] * WM * 0.5;
        double az = (double)w[base + 2] * WM * 0.5;
        double cx = cos(ax), sx = sin(ax);
        double cy = cos(ay), sy = sin(ay);
        double cz = cos(az), sz = sin(az);
        // RXX block (same on both subspaces): [[c, -is],[-is, c]]
        cd RXXb[4]  = {{cx, 0}, {0, -sx}, {0, -sx}, {cx, 0}};
        // RYY on (00,11): YY acts as [[0,-1],[-1,0]] -> [[c, +is],[+is, c]]
        cd RYY0[4]  = {{cy, 0}, {0,  sy}, {0,  sy}, {cy, 0}};
        // RYY on (01,10): YY acts as [[0,+1],[+1,0]] -> [[c, -is],[-is, c]]
        cd RYY1[4]  = {{cy, 0}, {0, -sy}, {0, -sy}, {cy, 0}};
        cd M0[4]; mm2(RYY0, RXXb, M0);
        cd M1[4]; mm2(RYY1, RXXb, M1);
        cd p0 = {cz, -sz};  // RZZ phase on 00/11
        cd p1 = {cz,  sz};  // RZZ phase on 01/10
        for (int i = 0; i < 4; i++) {
            cd g0 = cmuld(p0, M0[i]);
            cd g1 = cmuld(p1, M1[i]);
            d_G00[q][i] = make_float2((float)g0.re, (float)g0.im);
            d_G01[q][i] = make_float2((float)g1.re, (float)g1.im);
        }
    }
}

// ---------------------------------------------------------------------------
// State-vector gate sweeps (fp32, smem-resident tiles of 4096 amps)
// ---------------------------------------------------------------------------
__device__ __forceinline__ float2 cmulf(float2 a, float2 b) {
    return make_float2(a.x * b.x - a.y * b.y, a.x * b.y + a.y * b.x);
}
__device__ __forceinline__ float2 cmaddf(float2 a, float2 b, float2 c) {
    // a*b + c
    return make_float2(fmaf(a.x, b.x, fmaf(-a.y, b.y, c.x)),
                       fmaf(a.x, b.y, fmaf( a.y, b.x, c.y)));
}

// single-qubit gate on local bit lb of a 4096-amp tile
__device__ __forceinline__ void apply1(float2* sv, const float2* m, int lb, int tid) {
    float2 m00 = m[0], m01 = m[1], m10 = m[2], m11 = m[3];
    for (int p = tid; p < 2048; p += 256) {
        int i0 = ((p >> lb) << (lb + 1)) | (p & ((1 << lb) - 1));
        int i1 = i0 | (1 << lb);
        float2 a = sv[i0], b = sv[i1];
        sv[i0] = cmaddf(m01, b, cmulf(m00, a));
        sv[i1] = cmaddf(m11, b, cmulf(m10, a));
    }
}

// two-qubit chain gate on local bits (lb+1, lb): block g00 on (00,11), g01 on (01,10)
__device__ __forceinline__ void apply2(float2* sv, const float2* g00, const float2* g01,
                                       int lb, int tid) {
    float2 a00 = g00[0], a01 = g00[1], a10 = g00[2], a11 = g00[3];
    float2 b00 = g01[0], b01 = g01[1], b10 = g01[2], b11 = g01[3];
    for (int g = tid; g < 1024; g += 256) {
        int low  = g & ((1 << lb) - 1);
        int base = ((g >> lb) << (lb + 2)) | low;
        int e01 = base | (1 << lb);
        int e10 = base | (2 << lb);
        int e11 = base | (3 << lb);
        float2 v00 = sv[base], v11 = sv[e11];
        float2 v01 = sv[e01],  v10 = sv[e10];
        sv[base] = cmaddf(a01, v11, cmulf(a00, v00));
        sv[e11]  = cmaddf(a11, v11, cmulf(a10, v00));
        sv[e01]  = cmaddf(b01, v10, cmulf(b00, v01));
        sv[e10]  = cmaddf(b11, v10, cmulf(b10, v01));
    }
}

// Kernel A: tile = bits {0,1} U {10..19}. Applies: layer1 on qubits 0..9,
// chain q=0..8, layer2 on qubits 0..7. Reads x (real), writes g_state.
// local bit of global bit b>=10 is b-8; bits {0,1} are pure coalescing padding.
__global__ void __launch_bounds__(256) kA(const float* __restrict__ x) {
    __shared__ float2 sv[4096];
    int tid = threadIdx.x;
    int b   = blockIdx.x >> 8;
    int mid = blockIdx.x & 255;  // global bits 2..9
    const float* xb = x + ((size_t)b << NQ);
    float2* gb = g_state + ((size_t)b << NQ);

    for (int s = tid; s < 4096; s += 256) {
        int H = s >> 2, c2 = s & 3;
        int g = (H << 10) | (mid << 2) | c2;
        sv[s] = make_float2(xb[g], 0.0f);
    }
    __syncthreads();
    #pragma unroll
    for (int q = 0; q < 10; q++) { apply1(sv, d_U1[q], 11 - q, tid); __syncthreads(); }
    #pragma unroll
    for (int q = 0; q < 9; q++)  { apply2(sv, d_G00[q], d_G01[q], 10 - q, tid); __syncthreads(); }
    #pragma unroll
    for (int q = 0; q < 8; q++)  { apply1(sv, d_U2[q], 11 - q, tid); __syncthreads(); }
    for (int s = tid; s < 4096; s += 256) {
        int H = s >> 2, c2 = s & 3;
        int g = (H << 10) | (mid << 2) | c2;
        gb[g] = sv[s];
    }
}

// Kernel B: tile = contiguous low bits 0..11. Applies: layer1 on qubits 10..19,
// chain q=9..18, layer2 on qubits 8..19. (All commute correctly with kernel A's
// gates across the split.)
__global__ void __launch_bounds__(256) kB() {
    __shared__ float2 sv[4096];
    int tid = threadIdx.x;
    int b  = blockIdx.x >> 8;
    int hi = blockIdx.x & 255;  // global bits 12..19
    float2* gb = g_state + ((size_t)b << NQ) + ((size_t)hi << 12);

    for (int s = tid; s < 4096; s += 256) sv[s] = gb[s];
    __syncthreads();
    #pragma unroll
    for (int q = 10; q < 20; q++) { apply1(sv, d_U1[q], 19 - q, tid); __syncthreads(); }
    #pragma unroll
    for (int q = 9; q < 19; q++)  { apply2(sv, d_G00[q], d_G01[q], 18 - q, tid); __syncthreads(); }
    #pragma unroll
    for (int q = 8; q < 20; q++)  { apply1(sv, d_U2[q], 19 - q, tid); __syncthreads(); }
    for (int s = tid; s < 4096; s += 256) gb[s] = sv[s];
}

// ---------------------------------------------------------------------------
// Kernel C: rdm[b,a,c] = sum_t psi[b,t,a] * conj(psi[b,t,c])
// Batched 1024x1024x1024 complex syrk. Hermitian: only bi<=bj tiles computed,
// mirror written conjugated. Inner loop on packed fma.rn.f32x2:
//   acc(Re,Im) += (ar,ai)*(br,br) + (ai,-ar)*(bi,bi)
// ---------------------------------------------------------------------------
__device__ __forceinline__ unsigned long long pack2(float x, float y) {
    unsigned long long r;
    asm("mov.b64 %0, {%1, %2};" : "=l"(r) : "f"(x), "f"(y));
    return r;
}
__device__ __forceinline__ float2 unpack2(unsigned long long v) {
    float x, y;
    asm("mov.b64 {%0, %1}, %2;" : "=f"(x), "=f"(y) : "l"(v));
    return make_float2(x, y);
}
__device__ __forceinline__ void fma2(unsigned long long& d, unsigned long long a,
                                     unsigned long long b) {
    asm("fma.rn.f32x2 %0, %1, %2, %0;" : "+l"(d) : "l"(a), "l"(b));
}

#define NTILE 16        // 1024/64
#define NPAIRS 136      // 16*17/2

__global__ void __launch_bounds__(256) kC(float2* __restrict__ out) {
    __shared__ float2 As[16][64];
    __shared__ float2 Bs[16][64];
    int tid = threadIdx.x;
    int z = blockIdx.x;
    int b = z / NPAIRS;
    int pair = z - b * NPAIRS;
    int bi = 0;
    while (pair >= NTILE - bi) { pair -= NTILE - bi; bi++; }
    int bj = bi + pair;

    const float2* Mb = g_state + ((size_t)b << NQ);
    int a0 = bi << 6, c0 = bj << 6;
    int tx = tid & 15, ty = tid >> 4;
    int lr = tid >> 6, lcol = tid & 63;

    unsigned long long acc[4][4];
    #pragma unroll
    for (int i = 0; i < 4; i++)
        #pragma unroll
        for (int j = 0; j < 4; j++) acc[i][j] = 0ull;

    for (int k0 = 0; k0 < 1024; k0 += 16) {
        #pragma unroll
        for (int r = 0; r < 4; r++) {
            int kk = lr + r * 4;
            As[kk][lcol] = Mb[((k0 + kk) << 10) + a0 + lcol];
            Bs[kk][lcol] = Mb[((k0 + kk) << 10) + c0 + lcol];
        }
        __syncthreads();
        #pragma unroll
        for (int kk = 0; kk < 16; kk++) {
            unsigned long long ap[4], am[4], bre[4], bim[4];
            #pragma unroll
            for (int i = 0; i < 4; i++) {
                float2 a = As[kk][ty + 16 * i];
                ap[i] = pack2(a.x, a.y);    // (ar, ai)
                am[i] = pack2(a.y, -a.x);   // (ai, -ar)
            }
            #pragma unroll
            for (int j = 0; j < 4; j++) {
                float2 bv = Bs[kk][tx + 16 * j];
                bre[j] = pack2(bv.x, bv.x);
                bim[j] = pack2(bv.y, bv.y);
            }
            #pragma unroll
            for (int i = 0; i < 4; i++)
                #pragma unroll
                for (int j = 0; j < 4; j++) {
                    fma2(acc[i][j], ap[i], bre[j]);  // Re += ar*br ; Im += ai*br
                    fma2(acc[i][j], am[i], bim[j]);  // Re += ai*bi ; Im += -ar*bi
                }
        }
        __syncthreads();
    }

    float2* ob = out + ((size_t)b << NQ);
    #pragma unroll
    for (int i = 0; i < 4; i++) {
        int a = a0 + ty + 16 * i;
        #pragma unroll
        for (int j = 0; j < 4; j++) {
            int c = c0 + tx + 16 * j;
            float2 v = unpack2(acc[i][j]);
            ob[(a << 10) + c] = v;
            if (bi != bj) ob[(c << 10) + a] = make_float2(v.x, -v.y);
        }
    }
}

// ---------------------------------------------------------------------------
extern "C" void kernel_launch(void* const* d_in, const int* in_sizes, int n_in,
                              void* d_out, int out_size) {
    const float* x = (const float*)d_in[0];
    const float* w = (const float*)d_in[1];
    // d_in[2] = dimA (always 10, compiled in)
    (void)in_sizes; (void)n_in; (void)out_size;

    kprep<<<1, 64>>>(w);
    kA<<<BATCH * 256, 256>>>(x);
    kB<<<BATCH * 256, 256>>>();
    kC<<<BATCH * NPAIRS, 256>>>((float2*)d_out);
}

// round 3
// speedup vs baseline: 1.0033x; 1.0033x over previous
#include <cuda_runtime.h>

// ============================================================================
// QuConVXYZ: 20-qubit circuit (RX/RY/RZ layer, RXX/RYY/RZZ chain, RX/RY/RZ
// layer) on batch-4 state, then 10-qubit reduced density matrix.
//
// Key reductions:
//  - RZ*RY*RX per wire  -> one fused 2x2 complex gate
//  - RZZ*RYY*RXX per pair -> two 2x2 complex blocks on (00,11) and (01,10)
//  - whole circuit in 2 smem-tiled passes
//  - RDM = batched complex A^T conj(A) syrk with Hermitian-mirror writes,
//    inner loop on packed fma.rn.f32x2 (Re/Im lanes fused)
// ============================================================================

#define BATCH 4
#define NQ 20
#define DIM (1u << NQ)

__device__ float2 g_state[BATCH * DIM];  // 32 MB scratch

__device__ float2 d_U1[20][4];   // fused layer-1 single-qubit gates (row major 2x2)
__device__ float2 d_U2[20][4];   // fused layer-2 single-qubit gates
__device__ float2 d_G00[19][4];  // chain gate block on (|00>,|11>)
__device__ float2 d_G01[19][4];  // chain gate block on (|01>,|10>)

// ---------------------------------------------------------------------------
// Gate precompute (double precision, trivial cost)
// ---------------------------------------------------------------------------
struct cd { double re, im; };
__device__ __forceinline__ cd cmuld(cd a, cd b) {
    return {a.re * b.re - a.im * b.im, a.re * b.im + a.im * b.re};
}
__device__ __forceinline__ cd caddd(cd a, cd b) { return {a.re + b.re, a.im + b.im}; }
__device__ void mm2(const cd* A, const cd* B, cd* C) {
    C[0] = caddd(cmuld(A[0], B[0]), cmuld(A[1], B[2]));
    C[1] = caddd(cmuld(A[0], B[1]), cmuld(A[1], B[3]));
    C[2] = caddd(cmuld(A[2], B[0]), cmuld(A[3], B[2]));
    C[3] = caddd(cmuld(A[2], B[1]), cmuld(A[3], B[3]));
}

__global__ void kprep(const float* __restrict__ w) {
    int t = threadIdx.x;
    const double WM = 0.6324555320336759;  // sqrt(2)/sqrt(5)
    if (t < 40) {
        int q = t % 20;
        int base = (t < 20) ? 3 * q : (117 + 3 * q);  // layer1 | layer2 params
        double ax = (double)w[base]     * WM * 0.5;
        double ay = (double)w[base + 1] * WM * 0.5;
        double az = (double)w[base + 2] * WM * 0.5;
        double cx = cos(ax), sx = sin(ax);
        double cy = cos(ay), sy = sin(ay);
        double cz = cos(az), sz = sin(az);
        cd RX[4] = {{cx, 0}, {0, -sx}, {0, -sx}, {cx, 0}};
        cd RY[4] = {{cy, 0}, {-sy, 0}, {sy, 0}, {cy, 0}};
        cd RYX[4]; mm2(RY, RX, RYX);
        cd z0 = {cz, -sz}, z1 = {cz, sz};  // RZ = diag(e^{-ia}, e^{+ia})
        cd U[4] = {cmuld(z0, RYX[0]), cmuld(z0, RYX[1]),
                   cmuld(z1, RYX[2]), cmuld(z1, RYX[3])};
        float2 (*dst)[4] = (t < 20) ? d_U1 : d_U2;
        for (int i = 0; i < 4; i++) dst[q][i] = make_float2((float)U[i].re, (float)U[i].im);
    } else if (t < 59) {
        int q = t - 40;
        int base = 60 + 3 * q;
        double ax = (double)w[base]     * WM * 0.5;
        double ay = (double)w[base + 1] * WM * 0.5;
        double az = (double)w[base + 2] * WM * 0.5;
        double cx = cos(ax), sx = sin(ax);
        double cy = cos(ay), sy = sin(ay);
        double cz = cos(az), sz = sin(az);
        // RXX block (same on both subspaces): [[c, -is],[-is, c]]
        cd RXXb[4]  = {{cx, 0}, {0, -sx}, {0, -sx}, {cx, 0}};
        // RYY on (00,11): YY acts as [[0,-1],[-1,0]] -> [[c, +is],[+is, c]]
        cd RYY0[4]  = {{cy, 0}, {0,  sy}, {0,  sy}, {cy, 0}};
        // RYY on (01,10): YY acts as [[0,+1],[+1,0]] -> [[c, -is],[-is, c]]
        cd RYY1[4]  = {{cy, 0}, {0, -sy}, {0, -sy}, {cy, 0}};
        cd M0[4]; mm2(RYY0, RXXb, M0);
        cd M1[4]; mm2(RYY1, RXXb, M1);
        cd p0 = {cz, -sz};  // RZZ phase on 00/11
        cd p1 = {cz,  sz};  // RZZ phase on 01/10
        for (int i = 0; i < 4; i++) {
            cd g0 = cmuld(p0, M0[i]);
            cd g1 = cmuld(p1, M1[i]);
            d_G00[q][i] = make_float2((float)g0.re, (float)g0.im);
            d_G01[q][i] = make_float2((float)g1.re, (float)g1.im);
        }
    }
}

// ---------------------------------------------------------------------------
// State-vector gate sweeps (fp32, smem-resident tiles of 4096 amps)
// ---------------------------------------------------------------------------
__device__ __forceinline__ float2 cmulf(float2 a, float2 b) {
    return make_float2(a.x * b.x - a.y * b.y, a.x * b.y + a.y * b.x);
}
__device__ __forceinline__ float2 cmaddf(float2 a, float2 b, float2 c) {
    // a*b + c
    return make_float2(fmaf(a.x, b.x, fmaf(-a.y, b.y, c.x)),
                       fmaf(a.x, b.y, fmaf( a.y, b.x, c.y)));
}

// single-qubit gate on local bit lb of a 4096-amp tile
__device__ __forceinline__ void apply1(float2* sv, const float2* m, int lb, int tid) {
    float2 m00 = m[0], m01 = m[1], m10 = m[2], m11 = m[3];
    for (int p = tid; p < 2048; p += 256) {
        int i0 = ((p >> lb) << (lb + 1)) | (p & ((1 << lb) - 1));
        int i1 = i0 | (1 << lb);
        float2 a = sv[i0], b = sv[i1];
        sv[i0] = cmaddf(m01, b, cmulf(m00, a));
        sv[i1] = cmaddf(m11, b, cmulf(m10, a));
    }
}

// two-qubit chain gate on local bits (lb+1, lb): block g00 on (00,11), g01 on (01,10)
__device__ __forceinline__ void apply2(float2* sv, const float2* g00, const float2* g01,
                                       int lb, int tid) {
    float2 a00 = g00[0], a01 = g00[1], a10 = g00[2], a11 = g00[3];
    float2 b00 = g01[0], b01 = g01[1], b10 = g01[2], b11 = g01[3];
    for (int g = tid; g < 1024; g += 256) {
        int low  = g & ((1 << lb) - 1);
        int base = ((g >> lb) << (lb + 2)) | low;
        int e01 = base | (1 << lb);
        int e10 = base | (2 << lb);
        int e11 = base | (3 << lb);
        float2 v00 = sv[base], v11 = sv[e11];
        float2 v01 = sv[e01],  v10 = sv[e10];
        sv[base] = cmaddf(a01, v11, cmulf(a00, v00));
        sv[e11]  = cmaddf(a11, v11, cmulf(a10, v00));
        sv[e01]  = cmaddf(b01, v10, cmulf(b00, v01));
        sv[e10]  = cmaddf(b11, v10, cmulf(b10, v01));
    }
}

// Kernel A: tile = bits {0,1} U {10..19}. Applies: layer1 on qubits 0..9,
// chain q=0..8, layer2 on qubits 0..7. Reads x (real), writes g_state.
// local bit of global bit b>=10 is b-8; bits {0,1} are pure coalescing padding.
__global__ void __launch_bounds__(256) kA(const float* __restrict__ x) {
    __shared__ float2 sv[4096];
    int tid = threadIdx.x;
    int b   = blockIdx.x >> 8;
    int mid = blockIdx.x & 255;  // global bits 2..9
    const float* xb = x + ((size_t)b << NQ);
    float2* gb = g_state + ((size_t)b << NQ);

    for (int s = tid; s < 4096; s += 256) {
        int H = s >> 2, c2 = s & 3;
        int g = (H << 10) | (mid << 2) | c2;
        sv[s] = make_float2(xb[g], 0.0f);
    }
    __syncthreads();
    #pragma unroll
    for (int q = 0; q < 10; q++) { apply1(sv, d_U1[q], 11 - q, tid); __syncthreads(); }
    #pragma unroll
    for (int q = 0; q < 9; q++)  { apply2(sv, d_G00[q], d_G01[q], 10 - q, tid); __syncthreads(); }
    #pragma unroll
    for (int q = 0; q < 8; q++)  { apply1(sv, d_U2[q], 11 - q, tid); __syncthreads(); }
    for (int s = tid; s < 4096; s += 256) {
        int H = s >> 2, c2 = s & 3;
        int g = (H << 10) | (mid << 2) | c2;
        gb[g] = sv[s];
    }
}

// Kernel B: tile = contiguous low bits 0..11. Applies: layer1 on qubits 10..19,
// chain q=9..18, layer2 on qubits 8..19. (All commute correctly with kernel A's
// gates across the split.)
__global__ void __launch_bounds__(256) kB() {
    __shared__ float2 sv[4096];
    int tid = threadIdx.x;
    int b  = blockIdx.x >> 8;
    int hi = blockIdx.x & 255;  // global bits 12..19
    float2* gb = g_state + ((size_t)b << NQ) + ((size_t)hi << 12);

    for (int s = tid; s < 4096; s += 256) sv[s] = gb[s];
    __syncthreads();
    #pragma unroll
    for (int q = 10; q < 20; q++) { apply1(sv, d_U1[q], 19 - q, tid); __syncthreads(); }
    #pragma unroll
    for (int q = 9; q < 19; q++)  { apply2(sv, d_G00[q], d_G01[q], 18 - q, tid); __syncthreads(); }
    #pragma unroll
    for (int q = 8; q < 20; q++)  { apply1(sv, d_U2[q], 19 - q, tid); __syncthreads(); }
    for (int s = tid; s < 4096; s += 256) gb[s] = sv[s];
}

// ---------------------------------------------------------------------------
// Kernel C: rdm[b,a,c] = sum_t psi[b,t,a] * conj(psi[b,t,c])
// Batched 1024x1024x1024 complex syrk. Hermitian: only bi<=bj tiles computed,
// mirror written conjugated. Inner loop on packed fma.rn.f32x2:
//   acc(Re,Im) += (ar,ai)*(br,br) + (ai,-ar)*(bi,bi)
// ---------------------------------------------------------------------------
__device__ __forceinline__ unsigned long long pack2(float x, float y) {
    unsigned long long r;
    asm("mov.b64 %0, {%1, %2};" : "=l"(r) : "f"(x), "f"(y));
    return r;
}
__device__ __forceinline__ float2 unpack2(unsigned long long v) {
    float x, y;
    asm("mov.b64 {%0, %1}, %2;" : "=f"(x), "=f"(y) : "l"(v));
    return make_float2(x, y);
}
__device__ __forceinline__ void fma2(unsigned long long& d, unsigned long long a,
                                     unsigned long long b) {
    asm("fma.rn.f32x2 %0, %1, %2, %0;" : "+l"(d) : "l"(a), "l"(b));
}

#define NTILE 16        // 1024/64
#define NPAIRS 136      // 16*17/2

__global__ void __launch_bounds__(256) kC(float2* __restrict__ out) {
    __shared__ float2 As[16][64];
    __shared__ float2 Bs[16][64];
    int tid = threadIdx.x;
    int z = blockIdx.x;
    int b = z / NPAIRS;
    int pair = z - b * NPAIRS;
    int bi = 0;
    while (pair >= NTILE - bi) { pair -= NTILE - bi; bi++; }
    int bj = bi + pair;

    const float2* Mb = g_state + ((size_t)b << NQ);
    int a0 = bi << 6, c0 = bj << 6;
    int tx = tid & 15, ty = tid >> 4;
    int lr = tid >> 6, lcol = tid & 63;

    unsigned long long acc[4][4];
    #pragma unroll
    for (int i = 0; i < 4; i++)
        #pragma unroll
        for (int j = 0; j < 4; j++) acc[i][j] = 0ull;

    for (int k0 = 0; k0 < 1024; k0 += 16) {
        #pragma unroll
        for (int r = 0; r < 4; r++) {
            int kk = lr + r * 4;
            As[kk][lcol] = Mb[((k0 + kk) << 10) + a0 + lcol];
            Bs[kk][lcol] = Mb[((k0 + kk) << 10) + c0 + lcol];
        }
        __syncthreads();
        #pragma unroll
        for (int kk = 0; kk < 16; kk++) {
            unsigned long long ap[4], am[4], bre[4], bim[4];
            #pragma unroll
            for (int i = 0; i < 4; i++) {
                float2 a = As[kk][ty + 16 * i];
                ap[i] = pack2(a.x, a.y);    // (ar, ai)
                am[i] = pack2(a.y, -a.x);   // (ai, -ar)
            }
            #pragma unroll
            for (int j = 0; j < 4; j++) {
                float2 bv = Bs[kk][tx + 16 * j];
                bre[j] = pack2(bv.x, bv.x);
                bim[j] = pack2(bv.y, bv.y);
            }
            #pragma unroll
            for (int i = 0; i < 4; i++)
                #pragma unroll
                for (int j = 0; j < 4; j++) {
                    fma2(acc[i][j], ap[i], bre[j]);  // Re += ar*br ; Im += ai*br
                    fma2(acc[i][j], am[i], bim[j]);  // Re += ai*bi ; Im += -ar*bi
                }
        }
        __syncthreads();
    }

    float2* ob = out + ((size_t)b << NQ);
    #pragma unroll
    for (int i = 0; i < 4; i++) {
        int a = a0 + ty + 16 * i;
        #pragma unroll
        for (int j = 0; j < 4; j++) {
            int c = c0 + tx + 16 * j;
            float2 v = unpack2(acc[i][j]);
            ob[(a << 10) + c] = v;
            if (bi != bj) ob[(c << 10) + a] = make_float2(v.x, -v.y);
        }
    }
}

// ---------------------------------------------------------------------------
extern "C" void kernel_launch(void* const* d_in, const int* in_sizes, int n_in,
                              void* d_out, int out_size) {
    const float* x = (const float*)d_in[0];
    const float* w = (const float*)d_in[1];
    // d_in[2] = dimA (always 10, compiled in)
    (void)in_sizes; (void)n_in; (void)out_size;

    kprep<<<1, 64>>>(w);
    kA<<<BATCH * 256, 256>>>(x);
    kB<<<BATCH * 256, 256>>>();
    kC<<<BATCH * NPAIRS, 256>>>((float2*)d_out);
}

// round 5
// speedup vs baseline: 1.4761x; 1.4712x over previous
#include <cuda_runtime.h>
#include <cuda_bf16.h>
#include <cstdint>

#define BATCH 4
#define NQ 20
#define DIM (1u << NQ)

__device__ float2 g_state[BATCH * DIM];                 // 32 MB (kA -> kB)
__device__ __nv_bfloat162 g_Gh[(size_t)BATCH * 1024 * 1024];  // 16 MB: bf16-hi of G (K=2048)
__device__ __nv_bfloat162 g_Gl[(size_t)BATCH * 1024 * 1024];  // 16 MB: residual lo

__device__ float2 d_U1[20][4];
__device__ float2 d_U2[20][4];
__device__ float2 d_G00[19][4];
__device__ float2 d_G01[19][4];

// ---------------------------------------------------------------------------
// helpers
// ---------------------------------------------------------------------------
__device__ __forceinline__ uint32_t smem_u32(const void* p) {
    uint32_t a;
    asm("{ .reg .u64 t; cvta.to.shared.u64 t, %1; cvt.u32.u64 %0, t; }" : "=r"(a) : "l"(p));
    return a;
}
__device__ __forceinline__ void cpa16(uint32_t dst, const void* src) {
    asm volatile("cp.async.cg.shared.global [%0], [%1], 16;" :: "r"(dst), "l"(src));
}
#define CP_COMMIT() asm volatile("cp.async.commit_group;" ::: "memory")
#define CP_WAIT0()  asm volatile("cp.async.wait_group 0;" ::: "memory")
#define CP_WAIT1()  asm volatile("cp.async.wait_group 1;" ::: "memory")

#define LDM4(r, addr) \
    asm volatile("ldmatrix.sync.aligned.m8n8.x4.shared.b16 {%0,%1,%2,%3}, [%4];" \
        : "=r"((r)[0]), "=r"((r)[1]), "=r"((r)[2]), "=r"((r)[3]) : "r"(addr))

#define MMA(d, a, b0, b1) \
    asm volatile("mma.sync.aligned.m16n8k16.row.col.f32.bf16.bf16.f32 " \
        "{%0,%1,%2,%3}, {%4,%5,%6,%7}, {%8,%9}, {%0,%1,%2,%3};" \
        : "+f"((d)[0]), "+f"((d)[1]), "+f"((d)[2]), "+f"((d)[3]) \
        : "r"((a)[0]), "r"((a)[1]), "r"((a)[2]), "r"((a)[3]), "r"(b0), "r"(b1))

// ---------------------------------------------------------------------------
// Gate precompute
// ---------------------------------------------------------------------------
struct cd { double re, im; };
__device__ __forceinline__ cd cmuld(cd a, cd b) {
    return {a.re * b.re - a.im * b.im, a.re * b.im + a.im * b.re};
}
__device__ __forceinline__ cd caddd(cd a, cd b) { return {a.re + b.re, a.im + b.im}; }
__device__ void mm2(const cd* A, const cd* B, cd* C) {
    C[0] = caddd(cmuld(A[0], B[0]), cmuld(A[1], B[2]));
    C[1] = caddd(cmuld(A[0], B[1]), cmuld(A[1], B[3]));
    C[2] = caddd(cmuld(A[2], B[0]), cmuld(A[3], B[2]));
    C[3] = caddd(cmuld(A[2], B[1]), cmuld(A[3], B[3]));
}

__global__ void kprep(const float* __restrict__ w) {
    int t = threadIdx.x;
    const double WM = 0.6324555320336759;  // sqrt(2)/sqrt(5)
    if (t < 40) {
        int q = t % 20;
        int base = (t < 20) ? 3 * q : (117 + 3 * q);
        double ax = (double)w[base]     * WM * 0.5;
        double ay = (double)w[base + 1] * WM * 0.5;
        double az = (double)w[base + 2] * WM * 0.5;
        double cx = cos(ax), sx = sin(ax);
        double cy = cos(ay), sy = sin(ay);
        double cz = cos(az), sz = sin(az);
        cd RX[4] = {{cx, 0}, {0, -sx}, {0, -sx}, {cx, 0}};
        cd RY[4] = {{cy, 0}, {-sy, 0}, {sy, 0}, {cy, 0}};
        cd RYX[4]; mm2(RY, RX, RYX);
        cd z0 = {cz, -sz}, z1 = {cz, sz};
        cd U[4] = {cmuld(z0, RYX[0]), cmuld(z0, RYX[1]),
                   cmuld(z1, RYX[2]), cmuld(z1, RYX[3])};
        float2 (*dst)[4] = (t < 20) ? d_U1 : d_U2;
        for (int i = 0; i < 4; i++) dst[q][i] = make_float2((float)U[i].re, (float)U[i].im);
    } else if (t < 59) {
        int q = t - 40;
        int base = 60 + 3 * q;
        double ax = (double)w[base]     * WM * 0.5;
        double ay = (double)w[base + 1] * WM * 0.5;
        double az = (double)w[base + 2] * WM * 0.5;
        double cx = cos(ax), sx = sin(ax);
        double cy = cos(ay), sy = sin(ay);
        double cz = cos(az), sz = sin(az);
        cd RXXb[4] = {{cx, 0}, {0, -sx}, {0, -sx}, {cx, 0}};
        cd RYY0[4] = {{cy, 0}, {0,  sy}, {0,  sy}, {cy, 0}};
        cd RYY1[4] = {{cy, 0}, {0, -sy}, {0, -sy}, {cy, 0}};
        cd M0[4]; mm2(RYY0, RXXb, M0);
        cd M1[4]; mm2(RYY1, RXXb, M1);
        cd p0 = {cz, -sz}, p1 = {cz, sz};
        for (int i = 0; i < 4; i++) {
            cd g0 = cmuld(p0, M0[i]);
            cd g1 = cmuld(p1, M1[i]);
            d_G00[q][i] = make_float2((float)g0.re, (float)g0.im);
            d_G01[q][i] = make_float2((float)g1.re, (float)g1.im);
        }
    }
}

// ---------------------------------------------------------------------------
// Gate sweeps (proven fp32 versions, unchanged)
// ---------------------------------------------------------------------------
__device__ __forceinline__ float2 cmulf(float2 a, float2 b) {
    return make_float2(a.x * b.x - a.y * b.y, a.x * b.y + a.y * b.x);
}
__device__ __forceinline__ float2 cmaddf(float2 a, float2 b, float2 c) {
    return make_float2(fmaf(a.x, b.x, fmaf(-a.y, b.y, c.x)),
                       fmaf(a.x, b.y, fmaf( a.y, b.x, c.y)));
}

__device__ __forceinline__ void apply1(float2* sv, const float2* m, int lb, int tid) {
    float2 m00 = m[0], m01 = m[1], m10 = m[2], m11 = m[3];
    for (int p = tid; p < 2048; p += 256) {
        int i0 = ((p >> lb) << (lb + 1)) | (p & ((1 << lb) - 1));
        int i1 = i0 | (1 << lb);
        float2 a = sv[i0], b = sv[i1];
        sv[i0] = cmaddf(m01, b, cmulf(m00, a));
        sv[i1] = cmaddf(m11, b, cmulf(m10, a));
    }
}
__device__ __forceinline__ void apply2(float2* sv, const float2* g00, const float2* g01,
                                       int lb, int tid) {
    float2 a00 = g00[0], a01 = g00[1], a10 = g00[2], a11 = g00[3];
    float2 b00 = g01[0], b01 = g01[1], b10 = g01[2], b11 = g01[3];
    for (int g = tid; g < 1024; g += 256) {
        int low  = g & ((1 << lb) - 1);
        int base = ((g >> lb) << (lb + 2)) | low;
        int e01 = base | (1 << lb);
        int e10 = base | (2 << lb);
        int e11 = base | (3 << lb);
        float2 v00 = sv[base], v11 = sv[e11];
        float2 v01 = sv[e01],  v10 = sv[e10];
        sv[base] = cmaddf(a01, v11, cmulf(a00, v00));
        sv[e11]  = cmaddf(a11, v11, cmulf(a10, v00));
        sv[e01]  = cmaddf(b01, v10, cmulf(b00, v01));
        sv[e10]  = cmaddf(b11, v10, cmulf(b10, v01));
    }
}

// Kernel A: tile = bits {0,1} U {10..19}. layer1 q0..9, chain q0..8, layer2 q0..7
__global__ void __launch_bounds__(256) kA(const float* __restrict__ x) {
    __shared__ float2 sv[4096];
    int tid = threadIdx.x;
    int b   = blockIdx.x >> 8;
    int mid = blockIdx.x & 255;
    const float* xb = x + ((size_t)b << NQ);
    float2* gb = g_state + ((size_t)b << NQ);
    for (int s = tid; s < 4096; s += 256) {
        int H = s >> 2, c2 = s & 3;
        sv[s] = make_float2(xb[(H << 10) | (mid << 2) | c2], 0.0f);
    }
    __syncthreads();
    #pragma unroll
    for (int q = 0; q < 10; q++) { apply1(sv, d_U1[q], 11 - q, tid); __syncthreads(); }
    #pragma unroll
    for (int q = 0; q < 9; q++)  { apply2(sv, d_G00[q], d_G01[q], 10 - q, tid); __syncthreads(); }
    #pragma unroll
    for (int q = 0; q < 8; q++)  { apply1(sv, d_U2[q], 11 - q, tid); __syncthreads(); }
    for (int s = tid; s < 4096; s += 256) {
        int H = s >> 2, c2 = s & 3;
        gb[(H << 10) | (mid << 2) | c2] = sv[s];
    }
}

// Kernel B: tile = low bits 0..11. layer1 q10..19, chain q9..18, layer2 q8..19.
// Epilogue: bf16 hi/lo split of G, K-major (K=2048):
//   G[a,2t] = Re psi[t,a], G[a,2t+1] = Im psi[t,a]
__global__ void __launch_bounds__(256) kB() {
    __shared__ float2 sv[4096];
    int tid = threadIdx.x;
    int b   = blockIdx.x >> 8;
    int hib = blockIdx.x & 255;  // t bits 2..9
    float2* gb = g_state + ((size_t)b << NQ) + ((size_t)hib << 12);

    for (int s = tid; s < 4096; s += 256) sv[s] = gb[s];
    __syncthreads();
    #pragma unroll
    for (int q = 10; q < 20; q++) { apply1(sv, d_U1[q], 19 - q, tid); __syncthreads(); }
    #pragma unroll
    for (int q = 9; q < 19; q++)  { apply2(sv, d_G00[q], d_G01[q], 18 - q, tid); __syncthreads(); }
    #pragma unroll
    for (int q = 8; q < 20; q++)  { apply1(sv, d_U2[q], 19 - q, tid); __syncthreads(); }

    size_t mb = (size_t)b * (1024 * 1024);  // in bf162 units (1024 per row)
    int k2 = hib * 4;                       // bf162 column base
    for (int a = tid; a < 1024; a += 256) {
        __nv_bfloat162 gh[4], gl[4];
        #pragma unroll
        for (int t2 = 0; t2 < 4; t2++) {
            float2 v = sv[(t2 << 10) | a];
            __nv_bfloat162 h = __floats2bfloat162_rn(v.x, v.y);
            float hr = __bfloat162float(__low2bfloat16(h));
            float hi = __bfloat162float(__high2bfloat16(h));
            gh[t2] = h;
            gl[t2] = __floats2bfloat162_rn(v.x - hr, v.y - hi);
        }
        size_t off = mb + (size_t)a * 1024 + k2;
        *(uint4*)&g_Gh[off] = *(uint4*)gh;
        *(uint4*)&g_Gl[off] = *(uint4*)gl;
    }
}

// ---------------------------------------------------------------------------
// Kernel C: rdm = psi^T conj(psi) via bf16 mma.sync (3-term hi/lo split).
//   Re = G_a G_c^T ; Im = H_a G_c^T with H derived in-register:
//   H reg = halfword_swap(G reg) ^ 0x80000000   ((Re,Im) -> (Im,-Re))
// 128x128 Hermitian tile pairs (36/batch * 4 = 144 CTAs = one wave),
// 512 threads = 4x4 warps, warp tile 32x32, K-chunks of 32 double-buffered.
// ---------------------------------------------------------------------------
#define TPITCH 80                       // 64B data + 16B pad: conflict-free ldmatrix
#define TILE_SM (128 * TPITCH)          // 10240 B
#define STAGE_SM (4 * TILE_SM)          // Gh_a, Gl_a, Gh_c, Gl_c
#define SMEM_KC (2 * STAGE_SM)          // 81920 B

__device__ __forceinline__ void kc_load(uint32_t sb, int buf,
                                        const __nv_bfloat16* const* srcs,
                                        int kc, int tid) {
    int row = tid >> 2, c = tid & 3;
    uint32_t dst = sb + buf * STAGE_SM + row * TPITCH + c * 16;
    #pragma unroll
    for (int t = 0; t < 4; t++)
        cpa16(dst + t * TILE_SM, srcs[t] + (size_t)row * 2048 + kc + c * 8);
}

__global__ void __launch_bounds__(512, 1) kC(float2* __restrict__ out) {
    extern __shared__ char smc[];
    uint32_t sb = smem_u32(smc);
    int tid = threadIdx.x, lane = tid & 31, wid = tid >> 5;
    int wm = wid >> 2, wn = wid & 3;

    int z = blockIdx.x;
    int b = z / 36;
    int pair = z - b * 36;
    int bi = 0;
    while (pair >= 8 - bi) { pair -= 8 - bi; bi++; }
    int bj = bi + pair;
    int a0 = bi << 7, c0 = bj << 7;

    const __nv_bfloat16* Gh = (const __nv_bfloat16*)(g_Gh + (size_t)b * 1024 * 1024);
    const __nv_bfloat16* Gl = (const __nv_bfloat16*)(g_Gl + (size_t)b * 1024 * 1024);
    const __nv_bfloat16* srcs[4] = {
        Gh + (size_t)a0 * 2048, Gl + (size_t)a0 * 2048,
        Gh + (size_t)c0 * 2048, Gl + (size_t)c0 * 2048 };

    float accR[2][4][4], accI[2][4][4];
    #pragma unroll
    for (int i = 0; i < 2; i++)
        #pragma unroll
        for (int j = 0; j < 4; j++)
            #pragma unroll
            for (int k = 0; k < 4; k++) { accR[i][j][k] = 0.f; accI[i][j][k] = 0.f; }

    // ldmatrix lane-relative offset: row = lane&15, k-half = lane>>4
    uint32_t loff = (uint32_t)((lane & 15) * TPITCH + (lane >> 4) * 16);

    kc_load(sb, 0, srcs, 0, tid);
    CP_COMMIT();

    for (int s = 0; s < 64; s++) {
        if (s < 63) { kc_load(sb, (s + 1) & 1, srcs, (s + 1) * 32, tid); CP_COMMIT(); CP_WAIT1(); }
        else CP_WAIT0();
        __syncthreads();

        uint32_t st = sb + (s & 1) * STAGE_SM + loff;
        #pragma unroll
        for (int ks = 0; ks < 2; ks++) {
            uint32_t ko = (uint32_t)(ks * 32);
            uint32_t AH[2][4], AL[2][4], BH[2][4], BL[2][4];
            #pragma unroll
            for (int mt = 0; mt < 2; mt++) {
                uint32_t ra = st + (wm * 32 + mt * 16) * TPITCH + ko;
                LDM4(AH[mt], ra);
                LDM4(AL[mt], ra + TILE_SM);
            }
            #pragma unroll
            for (int p = 0; p < 2; p++) {
                uint32_t rb = st + 2 * TILE_SM + (wn * 32 + p * 16) * TPITCH + ko;
                LDM4(BH[p], rb);
                LDM4(BL[p], rb + TILE_SM);
            }
            #pragma unroll
            for (int mt = 0; mt < 2; mt++) {
                uint32_t HH[4], HL[4];
                #pragma unroll
                for (int i = 0; i < 4; i++) {
                    HH[i] = __byte_perm(AH[mt][i], AH[mt][i], 0x1032) ^ 0x80000000u;
                    HL[i] = __byte_perm(AL[mt][i], AL[mt][i], 0x1032) ^ 0x80000000u;
                }
                #pragma unroll
                for (int nt = 0; nt < 4; nt++) {
                    int p = nt >> 1, q = nt & 1;
                    uint32_t b0h = BH[p][q], b1h = BH[p][q + 2];
                    uint32_t b0l = BL[p][q], b1l = BL[p][q + 2];
                    MMA(accR[mt][nt], AH[mt], b0h, b1h);
                    MMA(accR[mt][nt], AH[mt], b0l, b1l);
                    MMA(accR[mt][nt], AL[mt], b0h, b1h);
                    MMA(accI[mt][nt], HH, b0h, b1h);
                    MMA(accI[mt][nt], HH, b0l, b1l);
                    MMA(accI[mt][nt], HL, b0h, b1h);
                }
            }
        }
        __syncthreads();
    }

    // epilogue: direct stores + conjugate-transposed mirror
    float2* ob = out + ((size_t)b << 20);
    int rg = a0 + wm * 32 + (lane >> 2);
    int cg = c0 + wn * 32 + 2 * (lane & 3);
    #pragma unroll
    for (int mt = 0; mt < 2; mt++) {
        #pragma unroll
        for (int nt = 0; nt < 4; nt++) {
            int r = rg + mt * 16;
            int c = cg + nt * 8;
            float* R = accR[mt][nt];
            float* I = accI[mt][nt];
            *(float4*)&ob[((size_t)r << 10) + c]       = make_float4(R[0], I[0], R[1], I[1]);
            *(float4*)&ob[((size_t)(r + 8) << 10) + c] = make_float4(R[2], I[2], R[3], I[3]);
            if (bi != bj) {
                ob[((size_t)c << 10) + r]           = make_float2(R[0], -I[0]);
                ob[((size_t)(c + 1) << 10) + r]     = make_float2(R[1], -I[1]);
                ob[((size_t)c << 10) + r + 8]       = make_float2(R[2], -I[2]);
                ob[((size_t)(c + 1) << 10) + r + 8] = make_float2(R[3], -I[3]);
            }
        }
    }
}

// ---------------------------------------------------------------------------
extern "C" void kernel_launch(void* const* d_in, const int* in_sizes, int n_in,
                              void* d_out, int out_size) {
    const float* x = (const float*)d_in[0];
    const float* w = (const float*)d_in[1];
    (void)in_sizes; (void)n_in; (void)out_size;

    cudaFuncSetAttribute(kC, cudaFuncAttributeMaxDynamicSharedMemorySize, SMEM_KC);

    kprep<<<1, 64>>>(w);
    kA<<<BATCH * 256, 256>>>(x);
    kB<<<BATCH * 256, 256>>>();
    kC<<<BATCH * 36, 512, SMEM_KC>>>((float2*)d_out);
}

// round 7
// speedup vs baseline: 1.4764x; 1.0002x over previous
#include <cuda_runtime.h>
#include <cuda_bf16.h>
#include <cstdint>

#define BATCH 4
#define NQ 20
#define DIM (1u << NQ)

__device__ float2 g_state[BATCH * DIM];                 // 32 MB (kA -> kB)
__device__ __nv_bfloat162 g_Gh[(size_t)BATCH * 1024 * 1024];  // 16 MB: bf16-hi of G (K=2048)
__device__ __nv_bfloat162 g_Gl[(size_t)BATCH * 1024 * 1024];  // 16 MB: residual lo

__device__ float2 d_U1[20][4];
__device__ float2 d_U2[20][4];
__device__ float2 d_G00[19][4];
__device__ float2 d_G01[19][4];

// ---------------------------------------------------------------------------
// helpers
// ---------------------------------------------------------------------------
__device__ __forceinline__ uint32_t smem_u32(const void* p) {
    uint32_t a;
    asm("{ .reg .u64 t; cvta.to.shared.u64 t, %1; cvt.u32.u64 %0, t; }" : "=r"(a) : "l"(p));
    return a;
}
__device__ __forceinline__ void cpa16(uint32_t dst, const void* src) {
    asm volatile("cp.async.cg.shared.global [%0], [%1], 16;" :: "r"(dst), "l"(src));
}
#define CP_COMMIT() asm volatile("cp.async.commit_group;" ::: "memory")
#define CP_WAIT0()  asm volatile("cp.async.wait_group 0;" ::: "memory")
#define CP_WAIT1()  asm volatile("cp.async.wait_group 1;" ::: "memory")

#define LDM4(r, addr) \
    asm volatile("ldmatrix.sync.aligned.m8n8.x4.shared.b16 {%0,%1,%2,%3}, [%4];" \
        : "=r"((r)[0]), "=r"((r)[1]), "=r"((r)[2]), "=r"((r)[3]) : "r"(addr))

#define MMA(d, a, b0, b1) \
    asm volatile("mma.sync.aligned.m16n8k16.row.col.f32.bf16.bf16.f32 " \
        "{%0,%1,%2,%3}, {%4,%5,%6,%7}, {%8,%9}, {%0,%1,%2,%3};" \
        : "+f"((d)[0]), "+f"((d)[1]), "+f"((d)[2]), "+f"((d)[3]) \
        : "r"((a)[0]), "r"((a)[1]), "r"((a)[2]), "r"((a)[3]), "r"(b0), "r"(b1))

// ---------------------------------------------------------------------------
// Gate precompute
// ---------------------------------------------------------------------------
struct cd { double re, im; };
__device__ __forceinline__ cd cmuld(cd a, cd b) {
    return {a.re * b.re - a.im * b.im, a.re * b.im + a.im * b.re};
}
__device__ __forceinline__ cd caddd(cd a, cd b) { return {a.re + b.re, a.im + b.im}; }
__device__ void mm2(const cd* A, const cd* B, cd* C) {
    C[0] = caddd(cmuld(A[0], B[0]), cmuld(A[1], B[2]));
    C[1] = caddd(cmuld(A[0], B[1]), cmuld(A[1], B[3]));
    C[2] = caddd(cmuld(A[2], B[0]), cmuld(A[3], B[2]));
    C[3] = caddd(cmuld(A[2], B[1]), cmuld(A[3], B[3]));
}

__global__ void kprep(const float* __restrict__ w) {
    int t = threadIdx.x;
    const double WM = 0.6324555320336759;  // sqrt(2)/sqrt(5)
    if (t < 40) {
        int q = t % 20;
        int base = (t < 20) ? 3 * q : (117 + 3 * q);
        double ax = (double)w[base]     * WM * 0.5;
        double ay = (double)w[base + 1] * WM * 0.5;
        double az = (double)w[base + 2] * WM * 0.5;
        double cx = cos(ax), sx = sin(ax);
        double cy = cos(ay), sy = sin(ay);
        double cz = cos(az), sz = sin(az);
        cd RX[4] = {{cx, 0}, {0, -sx}, {0, -sx}, {cx, 0}};
        cd RY[4] = {{cy, 0}, {-sy, 0}, {sy, 0}, {cy, 0}};
        cd RYX[4]; mm2(RY, RX, RYX);
        cd z0 = {cz, -sz}, z1 = {cz, sz};
        cd U[4] = {cmuld(z0, RYX[0]), cmuld(z0, RYX[1]),
                   cmuld(z1, RYX[2]), cmuld(z1, RYX[3])};
        float2 (*dst)[4] = (t < 20) ? d_U1 : d_U2;
        for (int i = 0; i < 4; i++) dst[q][i] = make_float2((float)U[i].re, (float)U[i].im);
    } else if (t < 59) {
        int q = t - 40;
        int base = 60 + 3 * q;
        double ax = (double)w[base]     * WM * 0.5;
        double ay = (double)w[base + 1] * WM * 0.5;
        double az = (double)w[base + 2] * WM * 0.5;
        double cx = cos(ax), sx = sin(ax);
        double cy = cos(ay), sy = sin(ay);
        double cz = cos(az), sz = sin(az);
        cd RXXb[4] = {{cx, 0}, {0, -sx}, {0, -sx}, {cx, 0}};
        cd RYY0[4] = {{cy, 0}, {0,  sy}, {0,  sy}, {cy, 0}};
        cd RYY1[4] = {{cy, 0}, {0, -sy}, {0, -sy}, {cy, 0}};
        cd M0[4]; mm2(RYY0, RXXb, M0);
        cd M1[4]; mm2(RYY1, RXXb, M1);
        cd p0 = {cz, -sz}, p1 = {cz, sz};
        for (int i = 0; i < 4; i++) {
            cd g0 = cmuld(p0, M0[i]);
            cd g1 = cmuld(p1, M1[i]);
            d_G00[q][i] = make_float2((float)g0.re, (float)g0.im);
            d_G01[q][i] = make_float2((float)g1.re, (float)g1.im);
        }
    }
}

// ---------------------------------------------------------------------------
// Gate sweeps (proven fp32 versions, unchanged)
// ---------------------------------------------------------------------------
__device__ __forceinline__ float2 cmulf(float2 a, float2 b) {
    return make_float2(a.x * b.x - a.y * b.y, a.x * b.y + a.y * b.x);
}
__device__ __forceinline__ float2 cmaddf(float2 a, float2 b, float2 c) {
    return make_float2(fmaf(a.x, b.x, fmaf(-a.y, b.y, c.x)),
                       fmaf(a.x, b.y, fmaf( a.y, b.x, c.y)));
}

__device__ __forceinline__ void apply1(float2* sv, const float2* m, int lb, int tid) {
    float2 m00 = m[0], m01 = m[1], m10 = m[2], m11 = m[3];
    for (int p = tid; p < 2048; p += 256) {
        int i0 = ((p >> lb) << (lb + 1)) | (p & ((1 << lb) - 1));
        int i1 = i0 | (1 << lb);
        float2 a = sv[i0], b = sv[i1];
        sv[i0] = cmaddf(m01, b, cmulf(m00, a));
        sv[i1] = cmaddf(m11, b, cmulf(m10, a));
    }
}
__device__ __forceinline__ void apply2(float2* sv, const float2* g00, const float2* g01,
                                       int lb, int tid) {
    float2 a00 = g00[0], a01 = g00[1], a10 = g00[2], a11 = g00[3];
    float2 b00 = g01[0], b01 = g01[1], b10 = g01[2], b11 = g01[3];
    for (int g = tid; g < 1024; g += 256) {
        int low  = g & ((1 << lb) - 1);
        int base = ((g >> lb) << (lb + 2)) | low;
        int e01 = base | (1 << lb);
        int e10 = base | (2 << lb);
        int e11 = base | (3 << lb);
        float2 v00 = sv[base], v11 = sv[e11];
        float2 v01 = sv[e01],  v10 = sv[e10];
        sv[base] = cmaddf(a01, v11, cmulf(a00, v00));
        sv[e11]  = cmaddf(a11, v11, cmulf(a10, v00));
        sv[e01]  = cmaddf(b01, v10, cmulf(b00, v01));
        sv[e10]  = cmaddf(b11, v10, cmulf(b10, v01));
    }
}

// Kernel A: tile = bits {0,1} U {10..19}. layer1 q0..9, chain q0..8, layer2 q0..7
__global__ void __launch_bounds__(256) kA(const float* __restrict__ x) {
    __shared__ float2 sv[4096];
    int tid = threadIdx.x;
    int b   = blockIdx.x >> 8;
    int mid = blockIdx.x & 255;
    const float* xb = x + ((size_t)b << NQ);
    float2* gb = g_state + ((size_t)b << NQ);
    for (int s = tid; s < 4096; s += 256) {
        int H = s >> 2, c2 = s & 3;
        sv[s] = make_float2(xb[(H << 10) | (mid << 2) | c2], 0.0f);
    }
    __syncthreads();
    #pragma unroll
    for (int q = 0; q < 10; q++) { apply1(sv, d_U1[q], 11 - q, tid); __syncthreads(); }
    #pragma unroll
    for (int q = 0; q < 9; q++)  { apply2(sv, d_G00[q], d_G01[q], 10 - q, tid); __syncthreads(); }
    #pragma unroll
    for (int q = 0; q < 8; q++)  { apply1(sv, d_U2[q], 11 - q, tid); __syncthreads(); }
    for (int s = tid; s < 4096; s += 256) {
        int H = s >> 2, c2 = s & 3;
        gb[(H << 10) | (mid << 2) | c2] = sv[s];
    }
}

// Kernel B: tile = low bits 0..11. layer1 q10..19, chain q9..18, layer2 q8..19.
// Epilogue: bf16 hi/lo split of G, K-major (K=2048):
//   G[a,2t] = Re psi[t,a], G[a,2t+1] = Im psi[t,a]
__global__ void __launch_bounds__(256) kB() {
    __shared__ float2 sv[4096];
    int tid = threadIdx.x;
    int b   = blockIdx.x >> 8;
    int hib = blockIdx.x & 255;  // t bits 2..9
    float2* gb = g_state + ((size_t)b << NQ) + ((size_t)hib << 12);

    for (int s = tid; s < 4096; s += 256) sv[s] = gb[s];
    __syncthreads();
    #pragma unroll
    for (int q = 10; q < 20; q++) { apply1(sv, d_U1[q], 19 - q, tid); __syncthreads(); }
    #pragma unroll
    for (int q = 9; q < 19; q++)  { apply2(sv, d_G00[q], d_G01[q], 18 - q, tid); __syncthreads(); }
    #pragma unroll
    for (int q = 8; q < 20; q++)  { apply1(sv, d_U2[q], 19 - q, tid); __syncthreads(); }

    size_t mb = (size_t)b * (1024 * 1024);  // in bf162 units (1024 per row)
    int k2 = hib * 4;                       // bf162 column base
    for (int a = tid; a < 1024; a += 256) {
        __nv_bfloat162 gh[4], gl[4];
        #pragma unroll
        for (int t2 = 0; t2 < 4; t2++) {
            float2 v = sv[(t2 << 10) | a];
            __nv_bfloat162 h = __floats2bfloat162_rn(v.x, v.y);
            float hr = __bfloat162float(__low2bfloat16(h));
            float hi = __bfloat162float(__high2bfloat16(h));
            gh[t2] = h;
            gl[t2] = __floats2bfloat162_rn(v.x - hr, v.y - hi);
        }
        size_t off = mb + (size_t)a * 1024 + k2;
        *(uint4*)&g_Gh[off] = *(uint4*)gh;
        *(uint4*)&g_Gl[off] = *(uint4*)gl;
    }
}

// ---------------------------------------------------------------------------
// Kernel C: rdm = psi^T conj(psi) via bf16 mma.sync (3-term hi/lo split).
//   Re = G_a G_c^T ; Im = H_a G_c^T with H derived in-register:
//   H reg = halfword_swap(G reg) ^ 0x80000000   ((Re,Im) -> (Im,-Re))
// 128x128 Hermitian tile pairs (36/batch * 4 = 144 CTAs = one wave),
// 512 threads = 4x4 warps, warp tile 32x32, K-chunks of 32 double-buffered.
// ---------------------------------------------------------------------------
#define TPITCH 80                       // 64B data + 16B pad: conflict-free ldmatrix
#define TILE_SM (128 * TPITCH)          // 10240 B
#define STAGE_SM (4 * TILE_SM)          // Gh_a, Gl_a, Gh_c, Gl_c
#define SMEM_KC (2 * STAGE_SM)          // 81920 B

__device__ __forceinline__ void kc_load(uint32_t sb, int buf,
                                        const __nv_bfloat16* const* srcs,
                                        int kc, int tid) {
    int row = tid >> 2, c = tid & 3;
    uint32_t dst = sb + buf * STAGE_SM + row * TPITCH + c * 16;
    #pragma unroll
    for (int t = 0; t < 4; t++)
        cpa16(dst + t * TILE_SM, srcs[t] + (size_t)row * 2048 + kc + c * 8);
}

__global__ void __launch_bounds__(512, 1) kC(float2* __restrict__ out) {
    extern __shared__ char smc[];
    uint32_t sb = smem_u32(smc);
    int tid = threadIdx.x, lane = tid & 31, wid = tid >> 5;
    int wm = wid >> 2, wn = wid & 3;

    int z = blockIdx.x;
    int b = z / 36;
    int pair = z - b * 36;
    int bi = 0;
    while (pair >= 8 - bi) { pair -= 8 - bi; bi++; }
    int bj = bi + pair;
    int a0 = bi << 7, c0 = bj << 7;

    const __nv_bfloat16* Gh = (const __nv_bfloat16*)(g_Gh + (size_t)b * 1024 * 1024);
    const __nv_bfloat16* Gl = (const __nv_bfloat16*)(g_Gl + (size_t)b * 1024 * 1024);
    const __nv_bfloat16* srcs[4] = {
        Gh + (size_t)a0 * 2048, Gl + (size_t)a0 * 2048,
        Gh + (size_t)c0 * 2048, Gl + (size_t)c0 * 2048 };

    float accR[2][4][4], accI[2][4][4];
    #pragma unroll
    for (int i = 0; i < 2; i++)
        #pragma unroll
        for (int j = 0; j < 4; j++)
            #pragma unroll
            for (int k = 0; k < 4; k++) { accR[i][j][k] = 0.f; accI[i][j][k] = 0.f; }

    // ldmatrix lane-relative offset: row = lane&15, k-half = lane>>4
    uint32_t loff = (uint32_t)((lane & 15) * TPITCH + (lane >> 4) * 16);

    kc_load(sb, 0, srcs, 0, tid);
    CP_COMMIT();

    for (int s = 0; s < 64; s++) {
        if (s < 63) { kc_load(sb, (s + 1) & 1, srcs, (s + 1) * 32, tid); CP_COMMIT(); CP_WAIT1(); }
        else CP_WAIT0();
        __syncthreads();

        uint32_t st = sb + (s & 1) * STAGE_SM + loff;
        #pragma unroll
        for (int ks = 0; ks < 2; ks++) {
            uint32_t ko = (uint32_t)(ks * 32);
            uint32_t AH[2][4], AL[2][4], BH[2][4], BL[2][4];
            #pragma unroll
            for (int mt = 0; mt < 2; mt++) {
                uint32_t ra = st + (wm * 32 + mt * 16) * TPITCH + ko;
                LDM4(AH[mt], ra);
                LDM4(AL[mt], ra + TILE_SM);
            }
            #pragma unroll
            for (int p = 0; p < 2; p++) {
                uint32_t rb = st + 2 * TILE_SM + (wn * 32 + p * 16) * TPITCH + ko;
                LDM4(BH[p], rb);
                LDM4(BL[p], rb + TILE_SM);
            }
            #pragma unroll
            for (int mt = 0; mt < 2; mt++) {
                uint32_t HH[4], HL[4];
                #pragma unroll
                for (int i = 0; i < 4; i++) {
                    HH[i] = __byte_perm(AH[mt][i], AH[mt][i], 0x1032) ^ 0x80000000u;
                    HL[i] = __byte_perm(AL[mt][i], AL[mt][i], 0x1032) ^ 0x80000000u;
                }
                #pragma unroll
                for (int nt = 0; nt < 4; nt++) {
                    int p = nt >> 1, q = nt & 1;
                    uint32_t b0h = BH[p][q], b1h = BH[p][q + 2];
                    uint32_t b0l = BL[p][q], b1l = BL[p][q + 2];
                    MMA(accR[mt][nt], AH[mt], b0h, b1h);
                    MMA(accR[mt][nt], AH[mt], b0l, b1l);
                    MMA(accR[mt][nt], AL[mt], b0h, b1h);
                    MMA(accI[mt][nt], HH, b0h, b1h);
                    MMA(accI[mt][nt], HH, b0l, b1l);
                    MMA(accI[mt][nt], HL, b0h, b1h);
                }
            }
        }
        __syncthreads();
    }

    // epilogue: direct stores + conjugate-transposed mirror
    float2* ob = out + ((size_t)b << 20);
    int rg = a0 + wm * 32 + (lane >> 2);
    int cg = c0 + wn * 32 + 2 * (lane & 3);
    #pragma unroll
    for (int mt = 0; mt < 2; mt++) {
        #pragma unroll
        for (int nt = 0; nt < 4; nt++) {
            int r = rg + mt * 16;
            int c = cg + nt * 8;
            float* R = accR[mt][nt];
            float* I = accI[mt][nt];
            *(float4*)&ob[((size_t)r << 10) + c]       = make_float4(R[0], I[0], R[1], I[1]);
            *(float4*)&ob[((size_t)(r + 8) << 10) + c] = make_float4(R[2], I[2], R[3], I[3]);
            if (bi != bj) {
                ob[((size_t)c << 10) + r]           = make_float2(R[0], -I[0]);
                ob[((size_t)(c + 1) << 10) + r]     = make_float2(R[1], -I[1]);
                ob[((size_t)c << 10) + r + 8]       = make_float2(R[2], -I[2]);
                ob[((size_t)(c + 1) << 10) + r + 8] = make_float2(R[3], -I[3]);
            }
        }
    }
}

// ---------------------------------------------------------------------------
extern "C" void kernel_launch(void* const* d_in, const int* in_sizes, int n_in,
                              void* d_out, int out_size) {
    const float* x = (const float*)d_in[0];
    const float* w = (const float*)d_in[1];
    (void)in_sizes; (void)n_in; (void)out_size;

    cudaFuncSetAttribute(kC, cudaFuncAttributeMaxDynamicSharedMemorySize, SMEM_KC);

    kprep<<<1, 64>>>(w);
    kA<<<BATCH * 256, 256>>>(x);
    kB<<<BATCH * 256, 256>>>();
    kC<<<BATCH * 36, 512, SMEM_KC>>>((float2*)d_out);
}

// round 10
// speedup vs baseline: 1.7396x; 1.1783x over previous
#include <cuda_runtime.h>
#include <cuda_bf16.h>
#include <cstdint>

#define BATCH 4
#define NQ 20
#define DIM (1u << NQ)

__device__ float2 g_state[BATCH * DIM];                 // 32 MB (kA -> kB)
__device__ __nv_bfloat162 g_Gh[(size_t)BATCH * 1024 * 1024];  // 16 MB: bf16-hi of G (K=2048)
__device__ __nv_bfloat162 g_Gl[(size_t)BATCH * 1024 * 1024];  // 16 MB: residual lo

__device__ float2 d_F[19][16];   // fused 4x4 chain gates (row-major, i=2*s_q+s_{q+1})

// ---------------------------------------------------------------------------
// helpers
// ---------------------------------------------------------------------------
__device__ __forceinline__ uint32_t smem_u32(const void* p) {
    uint32_t a;
    asm("{ .reg .u64 t; cvta.to.shared.u64 t, %1; cvt.u32.u64 %0, t; }" : "=r"(a) : "l"(p));
    return a;
}
__device__ __forceinline__ void cpa16(uint32_t dst, const void* src) {
    asm volatile("cp.async.cg.shared.global [%0], [%1], 16;" :: "r"(dst), "l"(src));
}
#define CP_COMMIT() asm volatile("cp.async.commit_group;" ::: "memory")
#define CP_WAIT0()  asm volatile("cp.async.wait_group 0;" ::: "memory")
#define CP_WAIT1()  asm volatile("cp.async.wait_group 1;" ::: "memory")

#define LDM4(r, addr) \
    asm volatile("ldmatrix.sync.aligned.m8n8.x4.shared.b16 {%0,%1,%2,%3}, [%4];" \
        : "=r"((r)[0]), "=r"((r)[1]), "=r"((r)[2]), "=r"((r)[3]) : "r"(addr))

#define MMA(d, a, b0, b1) \
    asm volatile("mma.sync.aligned.m16n8k16.row.col.f32.bf16.bf16.f32 " \
        "{%0,%1,%2,%3}, {%4,%5,%6,%7}, {%8,%9}, {%0,%1,%2,%3};" \
        : "+f"((d)[0]), "+f"((d)[1]), "+f"((d)[2]), "+f"((d)[3]) \
        : "r"((a)[0]), "r"((a)[1]), "r"((a)[2]), "r"((a)[3]), "r"(b0), "r"(b1))

// ---------------------------------------------------------------------------
// Gate precompute: fuse ALL singles into the 19 chain gates (fp64).
//   F(q,q+1) = (U2(q) (x) Q) * C(q,q+1) * (R (x) U1(q+1))
//   R = U1(0) for q==0 else I ;  Q = U2(19) for q==18 else I
// Validity: U1(q+1) precedes the FIRST chain touching wire q+1 (= chain q),
// U2(q) follows the LAST chain touching wire q (= chain q); disjoint-wire
// gates commute, so the fold reproduces the reference ordering exactly.
// ---------------------------------------------------------------------------
struct cd { double re, im; };
__device__ __forceinline__ cd cmuld(cd a, cd b) {
    return {a.re * b.re - a.im * b.im, a.re * b.im + a.im * b.re};
}
__device__ __forceinline__ cd caddd(cd a, cd b) { return {a.re + b.re, a.im + b.im}; }
__device__ void mm2(const cd* A, const cd* B, cd* C) {
    C[0] = caddd(cmuld(A[0], B[0]), cmuld(A[1], B[2]));
    C[1] = caddd(cmuld(A[0], B[1]), cmuld(A[1], B[3]));
    C[2] = caddd(cmuld(A[2], B[0]), cmuld(A[3], B[2]));
    C[3] = caddd(cmuld(A[2], B[1]), cmuld(A[3], B[3]));
}
__device__ void mm4(const cd* A, const cd* B, cd* C) {
    for (int i = 0; i < 4; i++)
        for (int j = 0; j < 4; j++) {
            cd s = {0, 0};
            for (int k = 0; k < 4; k++) s = caddd(s, cmuld(A[i * 4 + k], B[k * 4 + j]));
            C[i * 4 + j] = s;
        }
}
__device__ void kron2(const cd* A, const cd* B, cd* K) {
    for (int i0 = 0; i0 < 2; i0++)
        for (int i1 = 0; i1 < 2; i1++)
            for (int j0 = 0; j0 < 2; j0++)
                for (int j1 = 0; j1 < 2; j1++)
                    K[(2 * i0 + i1) * 4 + (2 * j0 + j1)] =
                        cmuld(A[i0 * 2 + j0], B[i1 * 2 + j1]);
}

__global__ void kprep(const float* __restrict__ w) {
    __shared__ double sU[2][20][4][2];  // [layer][q][elem][re/im]
    int t = threadIdx.x;
    const double WM = 0.6324555320336759;  // sqrt(2)/sqrt(5)
    if (t < 40) {
        int q = t % 20;
        int layer = t < 20 ? 0 : 1;
        int base = layer == 0 ? 3 * q : (117 + 3 * q);
        double ax = (double)w[base]     * WM * 0.5;
        double ay = (double)w[base + 1] * WM * 0.5;
        double az = (double)w[base + 2] * WM * 0.5;
        double cx = cos(ax), sx = sin(ax);
        double cy = cos(ay), sy = sin(ay);
        double cz = cos(az), sz = sin(az);
        cd RX[4] = {{cx, 0}, {0, -sx}, {0, -sx}, {cx, 0}};
        cd RY[4] = {{cy, 0}, {-sy, 0}, {sy, 0}, {cy, 0}};
        cd RYX[4]; mm2(RY, RX, RYX);
        cd z0 = {cz, -sz}, z1 = {cz, sz};
        cd U[4] = {cmuld(z0, RYX[0]), cmuld(z0, RYX[1]),
                   cmuld(z1, RYX[2]), cmuld(z1, RYX[3])};
        for (int i = 0; i < 4; i++) { sU[layer][q][i][0] = U[i].re; sU[layer][q][i][1] = U[i].im; }
    }
    __syncthreads();
    if (t < 19) {
        int q = t;
        int base = 60 + 3 * q;
        double ax = (double)w[base]     * WM * 0.5;
        double ay = (double)w[base + 1] * WM * 0.5;
        double az = (double)w[base + 2] * WM * 0.5;
        double cx = cos(ax), sx = sin(ax);
        double cy = cos(ay), sy = sin(ay);
        double cz = cos(az), sz = sin(az);
        cd RXXb[4] = {{cx, 0}, {0, -sx}, {0, -sx}, {cx, 0}};
        cd RYY0[4] = {{cy, 0}, {0,  sy}, {0,  sy}, {cy, 0}};
        cd RYY1[4] = {{cy, 0}, {0, -sy}, {0, -sy}, {cy, 0}};
        cd M0[4]; mm2(RYY0, RXXb, M0);
        cd M1[4]; mm2(RYY1, RXXb, M1);
        cd p0 = {cz, -sz}, p1 = {cz, sz};
        cd g00[4], g01[4];
        for (int i = 0; i < 4; i++) { g00[i] = cmuld(p0, M0[i]); g01[i] = cmuld(p1, M1[i]); }
        // 4x4 chain gate in basis i = 2*s_q + s_{q+1}
        cd C[16];
        for (int i = 0; i < 16; i++) C[i] = {0, 0};
        C[0 * 4 + 0] = g00[0]; C[0 * 4 + 3] = g00[1];
        C[3 * 4 + 0] = g00[2]; C[3 * 4 + 3] = g00[3];
        C[1 * 4 + 1] = g01[0]; C[1 * 4 + 2] = g01[1];
        C[2 * 4 + 1] = g01[2]; C[2 * 4 + 2] = g01[3];
        cd I2[4] = {{1, 0}, {0, 0}, {0, 0}, {1, 0}};
        cd R[4], S[4], P[4], Q[4];
        for (int i = 0; i < 4; i++) {
            R[i] = (q == 0)  ? cd{sU[0][0][i][0],  sU[0][0][i][1]}  : I2[i];
            S[i] = cd{sU[0][q + 1][i][0], sU[0][q + 1][i][1]};
            P[i] = cd{sU[1][q][i][0],     sU[1][q][i][1]};
            Q[i] = (q == 18) ? cd{sU[1][19][i][0], sU[1][19][i][1]} : I2[i];
        }
        cd PRE[16], POST[16], T[16], F[16];
        kron2(R, S, PRE);
        kron2(P, Q, POST);
        mm4(C, PRE, T);
        mm4(POST, T, F);
        for (int i = 0; i < 16; i++)
            d_F[q][i] = make_float2((float)F[i].re, (float)F[i].im);
    }
}

// ---------------------------------------------------------------------------
// Fused 4x4 gate sweep on local bits (lb+1 = wire q, lb = wire q+1)
// ---------------------------------------------------------------------------
__device__ __forceinline__ float2 cmulf(float2 a, float2 b) {
    return make_float2(a.x * b.x - a.y * b.y, a.x * b.y + a.y * b.x);
}
__device__ __forceinline__ float2 cmaddf(float2 a, float2 b, float2 c) {
    return make_float2(fmaf(a.x, b.x, fmaf(-a.y, b.y, c.x)),
                       fmaf(a.x, b.y, fmaf( a.y, b.x, c.y)));
}

__device__ __forceinline__ void apply4(float2* sv, const float2* __restrict__ G,
                                       int lb, int tid) {
    float2 g[16];
    #pragma unroll
    for (int i = 0; i < 16; i++) g[i] = G[i];
    #pragma unroll
    for (int grp = tid; grp < 1024; grp += 256) {
        int low  = grp & ((1 << lb) - 1);
        int base = ((grp >> lb) << (lb + 2)) | low;
        int i1 = base | (1 << lb);
        int i2 = base | (2 << lb);
        int i3 = base | (3 << lb);
        float2 v0 = sv[base], v1 = sv[i1], v2 = sv[i2], v3 = sv[i3];
        float2 o0 = cmaddf(g[3],  v3, cmaddf(g[2],  v2, cmaddf(g[1],  v1, cmulf(g[0],  v0))));
        float2 o1 = cmaddf(g[7],  v3, cmaddf(g[6],  v2, cmaddf(g[5],  v1, cmulf(g[4],  v0))));
        float2 o2 = cmaddf(g[11], v3, cmaddf(g[10], v2, cmaddf(g[9],  v1, cmulf(g[8],  v0))));
        float2 o3 = cmaddf(g[15], v3, cmaddf(g[14], v2, cmaddf(g[13], v1, cmulf(g[12], v0))));
        sv[base] = o0; sv[i1] = o1; sv[i2] = o2; sv[i3] = o3;
    }
}

// Kernel A: tile = bits {0,1} U {10..19}. Fused chains q=0..8
// (absorbs U1(0..9) and U2(0..8)). wire q local bit = 11-q, lb = 10-q.
__global__ void __launch_bounds__(256) kA(const float* __restrict__ x) {
    __shared__ float2 sv[4096];
    int tid = threadIdx.x;
    int b   = blockIdx.x >> 8;
    int mid = blockIdx.x & 255;
    const float* xb = x + ((size_t)b << NQ);
    float2* gb = g_state + ((size_t)b << NQ);
    for (int s = tid; s < 4096; s += 256) {
        int H = s >> 2, c2 = s & 3;
        sv[s] = make_float2(xb[(H << 10) | (mid << 2) | c2], 0.0f);
    }
    __syncthreads();
    #pragma unroll
    for (int q = 0; q < 9; q++) { apply4(sv, d_F[q], 10 - q, tid); __syncthreads(); }
    for (int s = tid; s < 4096; s += 256) {
        int H = s >> 2, c2 = s & 3;
        gb[(H << 10) | (mid << 2) | c2] = sv[s];
    }
}

// Kernel B: tile = low bits 0..11. Fused chains q=9..18
// (absorbs U1(10..19) and U2(9..19)). wire q local bit = 19-q, lb = 18-q.
// Epilogue: bf16 hi/lo split of G, K-major (K=2048):
//   G[a,2t] = Re psi[t,a], G[a,2t+1] = Im psi[t,a]
__global__ void __launch_bounds__(256) kB() {
    __shared__ float2 sv[4096];
    int tid = threadIdx.x;
    int b   = blockIdx.x >> 8;
    int hib = blockIdx.x & 255;  // t bits 2..9
    float2* gb = g_state + ((size_t)b << NQ) + ((size_t)hib << 12);

    for (int s = tid; s < 4096; s += 256) sv[s] = gb[s];
    __syncthreads();
    #pragma unroll
    for (int q = 9; q < 19; q++) { apply4(sv, d_F[q], 18 - q, tid); __syncthreads(); }

    size_t mb = (size_t)b * (1024 * 1024);  // bf162 units
    int k2 = hib * 4;
    for (int a = tid; a < 1024; a += 256) {
        __nv_bfloat162 gh[4], gl[4];
        #pragma unroll
        for (int t2 = 0; t2 < 4; t2++) {
            float2 v = sv[(t2 << 10) | a];
            __nv_bfloat162 h = __floats2bfloat162_rn(v.x, v.y);
            float hr = __bfloat162float(__low2bfloat16(h));
            float hi = __bfloat162float(__high2bfloat16(h));
            gh[t2] = h;
            gl[t2] = __floats2bfloat162_rn(v.x - hr, v.y - hi);
        }
        size_t off = mb + (size_t)a * 1024 + k2;
        *(uint4*)&g_Gh[off] = *(uint4*)gh;
        *(uint4*)&g_Gl[off] = *(uint4*)gl;
    }
}

// ---------------------------------------------------------------------------
// Kernel C: rdm via bf16 mma.sync, 3-term hi/lo split, K-chunk 64.
//   Re = G_a G_c^T ; Im = H_a G_c^T, H derived in-register:
//   H reg = halfword_swap(G reg) ^ 0x80000000
// ---------------------------------------------------------------------------
#define TPITCH 144                      // 128B data + 16B pad (conflict-free ldmatrix)
#define TILE_SM (128 * TPITCH)          // 18432 B
#define STAGE_SM (4 * TILE_SM)          // Gh_a, Gl_a, Gh_c, Gl_c
#define SMEM_KC (2 * STAGE_SM)          // 147456 B

__device__ __forceinline__ void kc_load(uint32_t sb, int buf,
                                        const __nv_bfloat16* const* srcs,
                                        int kc, int tid) {
    int row = tid & 127, c = tid >> 7;  // c in 0..3; cover chunks c and c+4
    uint32_t dst = sb + buf * STAGE_SM + row * TPITCH;
    #pragma unroll
    for (int t = 0; t < 4; t++) {
        const __nv_bfloat16* src = srcs[t] + (size_t)row * 2048 + kc;
        cpa16(dst + t * TILE_SM + c * 16,       src + c * 8);
        cpa16(dst + t * TILE_SM + (c + 4) * 16, src + (c + 4) * 8);
    }
}

__global__ void __launch_bounds__(512, 1) kC(float2* __restrict__ out) {
    extern __shared__ char smc[];
    uint32_t sb = smem_u32(smc);
    int tid = threadIdx.x, lane = tid & 31, wid = tid >> 5;
    int wm = wid >> 2, wn = wid & 3;

    int z = blockIdx.x;
    int b = z / 36;
    int pair = z - b * 36;
    int bi = 0;
    while (pair >= 8 - bi) { pair -= 8 - bi; bi++; }
    int bj = bi + pair;
    int a0 = bi << 7, c0 = bj << 7;

    const __nv_bfloat16* Gh = (const __nv_bfloat16*)(g_Gh + (size_t)b * 1024 * 1024);
    const __nv_bfloat16* Gl = (const __nv_bfloat16*)(g_Gl + (size_t)b * 1024 * 1024);
    const __nv_bfloat16* srcs[4] = {
        Gh + (size_t)a0 * 2048, Gl + (size_t)a0 * 2048,
        Gh + (size_t)c0 * 2048, Gl + (size_t)c0 * 2048 };

    float accR[2][4][4], accI[2][4][4];
    #pragma unroll
    for (int i = 0; i < 2; i++)
        #pragma unroll
        for (int j = 0; j < 4; j++)
            #pragma unroll
            for (int k = 0; k < 4; k++) { accR[i][j][k] = 0.f; accI[i][j][k] = 0.f; }

    uint32_t loff = (uint32_t)((lane & 15) * TPITCH + (lane >> 4) * 16);

    kc_load(sb, 0, srcs, 0, tid);
    CP_COMMIT();

    for (int s = 0; s < 32; s++) {
        if (s < 31) { kc_load(sb, (s + 1) & 1, srcs, (s + 1) * 64, tid); CP_COMMIT(); CP_WAIT1(); }
        else CP_WAIT0();
        __syncthreads();

        uint32_t st = sb + (s & 1) * STAGE_SM + loff;
        #pragma unroll
        for (int ks = 0; ks < 4; ks++) {
            uint32_t ko = (uint32_t)(ks * 32);
            uint32_t AH[2][4], AL[2][4], BH[2][4], BL[2][4];
            #pragma unroll
            for (int mt = 0; mt < 2; mt++) {
                uint32_t ra = st + (wm * 32 + mt * 16) * TPITCH + ko;
                LDM4(AH[mt], ra);
                LDM4(AL[mt], ra + TILE_SM);
            }
            #pragma unroll
            for (int p = 0; p < 2; p++) {
                uint32_t rb = st + 2 * TILE_SM + (wn * 32 + p * 16) * TPITCH + ko;
                LDM4(BH[p], rb);
                LDM4(BL[p], rb + TILE_SM);
            }
            #pragma unroll
            for (int mt = 0; mt < 2; mt++) {
                uint32_t HH[4], HL[4];
                #pragma unroll
                for (int i = 0; i < 4; i++) {
                    HH[i] = __byte_perm(AH[mt][i], AH[mt][i], 0x1032) ^ 0x80000000u;
                    HL[i] = __byte_perm(AL[mt][i], AL[mt][i], 0x1032) ^ 0x80000000u;
                }
                #pragma unroll
                for (int nt = 0; nt < 4; nt++) {
                    int p = nt >> 1, q = nt & 1;
                    uint32_t b0h = BH[p][q], b1h = BH[p][q + 2];
                    uint32_t b0l = BL[p][q], b1l = BL[p][q + 2];
                    MMA(accR[mt][nt], AH[mt], b0h, b1h);
                    MMA(accR[mt][nt], AH[mt], b0l, b1l);
                    MMA(accR[mt][nt], AL[mt], b0h, b1h);
                    MMA(accI[mt][nt], HH, b0h, b1h);
                    MMA(accI[mt][nt], HH, b0l, b1l);
                    MMA(accI[mt][nt], HL, b0h, b1h);
                }
            }
        }
        __syncthreads();
    }

    // epilogue: direct stores + conjugate-transposed mirror
    float2* ob = out + ((size_t)b << 20);
    int rg = a0 + wm * 32 + (lane >> 2);
    int cg = c0 + wn * 32 + 2 * (lane & 3);
    #pragma unroll
    for (int mt = 0; mt < 2; mt++) {
        #pragma unroll
        for (int nt = 0; nt < 4; nt++) {
            int r = rg + mt * 16;
            int c = cg + nt * 8;
            float* R = accR[mt][nt];
            float* I = accI[mt][nt];
            *(float4*)&ob[((size_t)r << 10) + c]       = make_float4(R[0], I[0], R[1], I[1]);
            *(float4*)&ob[((size_t)(r + 8) << 10) + c] = make_float4(R[2], I[2], R[3], I[3]);
            if (bi != bj) {
                ob[((size_t)c << 10) + r]           = make_float2(R[0], -I[0]);
                ob[((size_t)(c + 1) << 10) + r]     = make_float2(R[1], -I[1]);
                ob[((size_t)c << 10) + r + 8]       = make_float2(R[2], -I[2]);
                ob[((size_t)(c + 1) << 10) + r + 8] = make_float2(R[3], -I[3]);
            }
        }
    }
}

// ---------------------------------------------------------------------------
extern "C" void kernel_launch(void* const* d_in, const int* in_sizes, int n_in,
                              void* d_out, int out_size) {
    const float* x = (const float*)d_in[0];
    const float* w = (const float*)d_in[1];
    (void)in_sizes; (void)n_in; (void)out_size;

    cudaFuncSetAttribute(kC, cudaFuncAttributeMaxDynamicSharedMemorySize, SMEM_KC);

    kprep<<<1, 64>>>(w);
    kA<<<BATCH * 256, 256>>>(x);
    kB<<<BATCH * 256, 256>>>();
    kC<<<BATCH * 36, 512, SMEM_KC>>>((float2*)d_out);
}

// round 11
// speedup vs baseline: 1.9735x; 1.1344x over previous
#include <cuda_runtime.h>
#include <cuda_bf16.h>
#include <cstdint>

#define BATCH 4
#define NQ 20
#define DIM (1u << NQ)

__device__ float2 g_state[BATCH * DIM];                 // 32 MB (kA -> kB)
__device__ __nv_bfloat162 g_Gh[(size_t)BATCH * 1024 * 1024];  // 16 MB: bf16-hi of G (K=2048)
__device__ __nv_bfloat162 g_Gl[(size_t)BATCH * 1024 * 1024];  // 16 MB: residual lo

__device__ float2 d_F[19][16];   // fused 4x4 chain gates (row-major, i=2*s_q+s_{q+1})

// ---------------------------------------------------------------------------
// helpers
// ---------------------------------------------------------------------------
__device__ __forceinline__ uint32_t smem_u32(const void* p) {
    uint32_t a;
    asm("{ .reg .u64 t; cvta.to.shared.u64 t, %1; cvt.u32.u64 %0, t; }" : "=r"(a) : "l"(p));
    return a;
}
__device__ __forceinline__ void cpa16(uint32_t dst, const void* src) {
    asm volatile("cp.async.cg.shared.global [%0], [%1], 16;" :: "r"(dst), "l"(src));
}
#define CP_COMMIT() asm volatile("cp.async.commit_group;" ::: "memory")
#define CP_WAIT0()  asm volatile("cp.async.wait_group 0;" ::: "memory")
#define CP_WAIT1()  asm volatile("cp.async.wait_group 1;" ::: "memory")

#define LDM4(r, addr) \
    asm volatile("ldmatrix.sync.aligned.m8n8.x4.shared.b16 {%0,%1,%2,%3}, [%4];" \
        : "=r"((r)[0]), "=r"((r)[1]), "=r"((r)[2]), "=r"((r)[3]) : "r"(addr))

#define MMA(d, a, b0, b1) \
    asm volatile("mma.sync.aligned.m16n8k16.row.col.f32.bf16.bf16.f32 " \
        "{%0,%1,%2,%3}, {%4,%5,%6,%7}, {%8,%9}, {%0,%1,%2,%3};" \
        : "+f"((d)[0]), "+f"((d)[1]), "+f"((d)[2]), "+f"((d)[3]) \
        : "r"((a)[0]), "r"((a)[1]), "r"((a)[2]), "r"((a)[3]), "r"(b0), "r"(b1))

// ---------------------------------------------------------------------------
// Gate precompute: fuse ALL singles into the 19 chain gates (fp64).
//   F(q,q+1) = (U2(q) (x) Q) * C(q,q+1) * (R (x) U1(q+1))
//   R = U1(0) for q==0 else I ;  Q = U2(19) for q==18 else I
// ---------------------------------------------------------------------------
struct cd { double re, im; };
__device__ __forceinline__ cd cmuld(cd a, cd b) {
    return {a.re * b.re - a.im * b.im, a.re * b.im + a.im * b.re};
}
__device__ __forceinline__ cd caddd(cd a, cd b) { return {a.re + b.re, a.im + b.im}; }
__device__ void mm2(const cd* A, const cd* B, cd* C) {
    C[0] = caddd(cmuld(A[0], B[0]), cmuld(A[1], B[2]));
    C[1] = caddd(cmuld(A[0], B[1]), cmuld(A[1], B[3]));
    C[2] = caddd(cmuld(A[2], B[0]), cmuld(A[3], B[2]));
    C[3] = caddd(cmuld(A[2], B[1]), cmuld(A[3], B[3]));
}
__device__ void mm4(const cd* A, const cd* B, cd* C) {
    for (int i = 0; i < 4; i++)
        for (int j = 0; j < 4; j++) {
            cd s = {0, 0};
            for (int k = 0; k < 4; k++) s = caddd(s, cmuld(A[i * 4 + k], B[k * 4 + j]));
            C[i * 4 + j] = s;
        }
}
__device__ void kron2(const cd* A, const cd* B, cd* K) {
    for (int i0 = 0; i0 < 2; i0++)
        for (int i1 = 0; i1 < 2; i1++)
            for (int j0 = 0; j0 < 2; j0++)
                for (int j1 = 0; j1 < 2; j1++)
                    K[(2 * i0 + i1) * 4 + (2 * j0 + j1)] =
                        cmuld(A[i0 * 2 + j0], B[i1 * 2 + j1]);
}

__global__ void kprep(const float* __restrict__ w) {
    __shared__ double sU[2][20][4][2];  // [layer][q][elem][re/im]
    int t = threadIdx.x;
    const double WM = 0.6324555320336759;  // sqrt(2)/sqrt(5)
    if (t < 40) {
        int q = t % 20;
        int layer = t < 20 ? 0 : 1;
        int base = layer == 0 ? 3 * q : (117 + 3 * q);
        double ax = (double)w[base]     * WM * 0.5;
        double ay = (double)w[base + 1] * WM * 0.5;
        double az = (double)w[base + 2] * WM * 0.5;
        double cx = cos(ax), sx = sin(ax);
        double cy = cos(ay), sy = sin(ay);
        double cz = cos(az), sz = sin(az);
        cd RX[4] = {{cx, 0}, {0, -sx}, {0, -sx}, {cx, 0}};
        cd RY[4] = {{cy, 0}, {-sy, 0}, {sy, 0}, {cy, 0}};
        cd RYX[4]; mm2(RY, RX, RYX);
        cd z0 = {cz, -sz}, z1 = {cz, sz};
        cd U[4] = {cmuld(z0, RYX[0]), cmuld(z0, RYX[1]),
                   cmuld(z1, RYX[2]), cmuld(z1, RYX[3])};
        for (int i = 0; i < 4; i++) { sU[layer][q][i][0] = U[i].re; sU[layer][q][i][1] = U[i].im; }
    }
    __syncthreads();
    if (t < 19) {
        int q = t;
        int base = 60 + 3 * q;
        double ax = (double)w[base]     * WM * 0.5;
        double ay = (double)w[base + 1] * WM * 0.5;
        double az = (double)w[base + 2] * WM * 0.5;
        double cx = cos(ax), sx = sin(ax);
        double cy = cos(ay), sy = sin(ay);
        double cz = cos(az), sz = sin(az);
        cd RXXb[4] = {{cx, 0}, {0, -sx}, {0, -sx}, {cx, 0}};
        cd RYY0[4] = {{cy, 0}, {0,  sy}, {0,  sy}, {cy, 0}};
        cd RYY1[4] = {{cy, 0}, {0, -sy}, {0, -sy}, {cy, 0}};
        cd M0[4]; mm2(RYY0, RXXb, M0);
        cd M1[4]; mm2(RYY1, RXXb, M1);
        cd p0 = {cz, -sz}, p1 = {cz, sz};
        cd g00[4], g01[4];
        for (int i = 0; i < 4; i++) { g00[i] = cmuld(p0, M0[i]); g01[i] = cmuld(p1, M1[i]); }
        cd C[16];
        for (int i = 0; i < 16; i++) C[i] = {0, 0};
        C[0 * 4 + 0] = g00[0]; C[0 * 4 + 3] = g00[1];
        C[3 * 4 + 0] = g00[2]; C[3 * 4 + 3] = g00[3];
        C[1 * 4 + 1] = g01[0]; C[1 * 4 + 2] = g01[1];
        C[2 * 4 + 1] = g01[2]; C[2 * 4 + 2] = g01[3];
        cd I2[4] = {{1, 0}, {0, 0}, {0, 0}, {1, 0}};
        cd R[4], S[4], P[4], Q[4];
        for (int i = 0; i < 4; i++) {
            R[i] = (q == 0)  ? cd{sU[0][0][i][0],  sU[0][0][i][1]}  : I2[i];
            S[i] = cd{sU[0][q + 1][i][0], sU[0][q + 1][i][1]};
            P[i] = cd{sU[1][q][i][0],     sU[1][q][i][1]};
            Q[i] = (q == 18) ? cd{sU[1][19][i][0], sU[1][19][i][1]} : I2[i];
        }
        cd PRE[16], POST[16], T[16], F[16];
        kron2(R, S, PRE);
        kron2(P, Q, POST);
        mm4(C, PRE, T);
        mm4(POST, T, F);
        for (int i = 0; i < 16; i++)
            d_F[q][i] = make_float2((float)F[i].re, (float)F[i].im);
    }
}

// ---------------------------------------------------------------------------
// Fused 4x4 gate sweep on local bits (lb+1 = wire q, lb = wire q+1)
// ---------------------------------------------------------------------------
__device__ __forceinline__ float2 cmulf(float2 a, float2 b) {
    return make_float2(a.x * b.x - a.y * b.y, a.x * b.y + a.y * b.x);
}
__device__ __forceinline__ float2 cmaddf(float2 a, float2 b, float2 c) {
    return make_float2(fmaf(a.x, b.x, fmaf(-a.y, b.y, c.x)),
                       fmaf(a.x, b.y, fmaf( a.y, b.x, c.y)));
}

__device__ __forceinline__ void apply4(float2* sv, const float2* __restrict__ G,
                                       int lb, int tid) {
    float2 g[16];
    #pragma unroll
    for (int i = 0; i < 16; i++) g[i] = G[i];
    #pragma unroll
    for (int grp = tid; grp < 1024; grp += 256) {
        int low  = grp & ((1 << lb) - 1);
        int base = ((grp >> lb) << (lb + 2)) | low;
        int i1 = base | (1 << lb);
        int i2 = base | (2 << lb);
        int i3 = base | (3 << lb);
        float2 v0 = sv[base], v1 = sv[i1], v2 = sv[i2], v3 = sv[i3];
        float2 o0 = cmaddf(g[3],  v3, cmaddf(g[2],  v2, cmaddf(g[1],  v1, cmulf(g[0],  v0))));
        float2 o1 = cmaddf(g[7],  v3, cmaddf(g[6],  v2, cmaddf(g[5],  v1, cmulf(g[4],  v0))));
        float2 o2 = cmaddf(g[11], v3, cmaddf(g[10], v2, cmaddf(g[9],  v1, cmulf(g[8],  v0))));
        float2 o3 = cmaddf(g[15], v3, cmaddf(g[14], v2, cmaddf(g[13], v1, cmulf(g[12], v0))));
        sv[base] = o0; sv[i1] = o1; sv[i2] = o2; sv[i3] = o3;
    }
}

// Kernel A: tile = bits {0,1} U {10..19}. Fused chains q=0..8
__global__ void __launch_bounds__(256) kA(const float* __restrict__ x) {
    __shared__ float2 sv[4096];
    int tid = threadIdx.x;
    int b   = blockIdx.x >> 8;
    int mid = blockIdx.x & 255;
    const float* xb = x + ((size_t)b << NQ);
    float2* gb = g_state + ((size_t)b << NQ);
    for (int s = tid; s < 4096; s += 256) {
        int H = s >> 2, c2 = s & 3;
        sv[s] = make_float2(xb[(H << 10) | (mid << 2) | c2], 0.0f);
    }
    __syncthreads();
    #pragma unroll
    for (int q = 0; q < 9; q++) { apply4(sv, d_F[q], 10 - q, tid); __syncthreads(); }
    for (int s = tid; s < 4096; s += 256) {
        int H = s >> 2, c2 = s & 3;
        gb[(H << 10) | (mid << 2) | c2] = sv[s];
    }
}

// Kernel B: tile = low bits 0..11. Fused chains q=9..18.
// Epilogue: bf16 hi/lo split of G, K-major (K=2048).
__global__ void __launch_bounds__(256) kB() {
    __shared__ float2 sv[4096];
    int tid = threadIdx.x;
    int b   = blockIdx.x >> 8;
    int hib = blockIdx.x & 255;  // t bits 2..9
    float2* gb = g_state + ((size_t)b << NQ) + ((size_t)hib << 12);

    for (int s = tid; s < 4096; s += 256) sv[s] = gb[s];
    __syncthreads();
    #pragma unroll
    for (int q = 9; q < 19; q++) { apply4(sv, d_F[q], 18 - q, tid); __syncthreads(); }

    size_t mb = (size_t)b * (1024 * 1024);  // bf162 units
    int k2 = hib * 4;
    for (int a = tid; a < 1024; a += 256) {
        __nv_bfloat162 gh[4], gl[4];
        #pragma unroll
        for (int t2 = 0; t2 < 4; t2++) {
            float2 v = sv[(t2 << 10) | a];
            __nv_bfloat162 h = __floats2bfloat162_rn(v.x, v.y);
            float hr = __bfloat162float(__low2bfloat16(h));
            float hi = __bfloat162float(__high2bfloat16(h));
            gh[t2] = h;
            gl[t2] = __floats2bfloat162_rn(v.x - hr, v.y - hi);
        }
        size_t off = mb + (size_t)a * 1024 + k2;
        *(uint4*)&g_Gh[off] = *(uint4*)gh;
        *(uint4*)&g_Gl[off] = *(uint4*)gl;
    }
}

// ---------------------------------------------------------------------------
// Kernel C: rdm via bf16 mma.sync, 3-term hi/lo split.
// R7-proven geometry (TPITCH 80, K-chunk 32) + 3-stage cp.async ring
// (prefetch distance 2) + single __syncthreads per stage.
//   Re = G_a G_c^T ; Im = H_a G_c^T, H derived in-register:
//   H reg = halfword_swap(G reg) ^ 0x80000000
// ---------------------------------------------------------------------------
#define TPITCH 80                       // 64B data + 16B pad: conflict-free ldmatrix
#define TILE_SM (128 * TPITCH)          // 10240 B
#define STAGE_SM (4 * TILE_SM)          // Gh_a, Gl_a, Gh_c, Gl_c = 40960 B
#define NSTAGE 3
#define SMEM_KC (NSTAGE * STAGE_SM)     // 122880 B

__device__ __forceinline__ void kc_load(uint32_t sb, int buf,
                                        const __nv_bfloat16* const* srcs,
                                        int kc, int tid) {
    int row = tid >> 2, c = tid & 3;
    uint32_t dst = sb + buf * STAGE_SM + row * TPITCH + c * 16;
    #pragma unroll
    for (int t = 0; t < 4; t++)
        cpa16(dst + t * TILE_SM, srcs[t] + (size_t)row * 2048 + kc + c * 8);
}

__global__ void __launch_bounds__(512, 1) kC(float2* __restrict__ out) {
    extern __shared__ char smc[];
    uint32_t sb = smem_u32(smc);
    int tid = threadIdx.x, lane = tid & 31, wid = tid >> 5;
    int wm = wid >> 2, wn = wid & 3;

    int z = blockIdx.x;
    int b = z / 36;
    int pair = z - b * 36;
    int bi = 0;
    while (pair >= 8 - bi) { pair -= 8 - bi; bi++; }
    int bj = bi + pair;
    int a0 = bi << 7, c0 = bj << 7;

    const __nv_bfloat16* Gh = (const __nv_bfloat16*)(g_Gh + (size_t)b * 1024 * 1024);
    const __nv_bfloat16* Gl = (const __nv_bfloat16*)(g_Gl + (size_t)b * 1024 * 1024);
    const __nv_bfloat16* srcs[4] = {
        Gh + (size_t)a0 * 2048, Gl + (size_t)a0 * 2048,
        Gh + (size_t)c0 * 2048, Gl + (size_t)c0 * 2048 };

    float accR[2][4][4], accI[2][4][4];
    #pragma unroll
    for (int i = 0; i < 2; i++)
        #pragma unroll
        for (int j = 0; j < 4; j++)
            #pragma unroll
            for (int k = 0; k < 4; k++) { accR[i][j][k] = 0.f; accI[i][j][k] = 0.f; }

    uint32_t loff = (uint32_t)((lane & 15) * TPITCH + (lane >> 4) * 16);

    // prefetch stages 0 and 1 (distance-2 pipeline)
    kc_load(sb, 0, srcs, 0, tid);
    CP_COMMIT();
    kc_load(sb, 1, srcs, 32, tid);
    CP_COMMIT();

    int buf = 0;
    for (int s = 0; s < 64; s++) {
        if (s < 63) CP_WAIT1(); else CP_WAIT0();  // stage s arrived (s+1 may be in flight)
        __syncthreads();  // all threads' stage-s data visible; prior consumption of
                          // buf (s+2)%3 finished -> safe to overwrite it below
        if (s + 2 < 64) {
            int nbuf = buf + 2; if (nbuf >= NSTAGE) nbuf -= NSTAGE;
            kc_load(sb, nbuf, srcs, (s + 2) * 32, tid);
            CP_COMMIT();
        }

        uint32_t st = sb + buf * STAGE_SM + loff;
        #pragma unroll
        for (int ks = 0; ks < 2; ks++) {
            uint32_t ko = (uint32_t)(ks * 32);
            uint32_t AH[2][4], AL[2][4], BH[2][4], BL[2][4];
            #pragma unroll
            for (int mt = 0; mt < 2; mt++) {
                uint32_t ra = st + (wm * 32 + mt * 16) * TPITCH + ko;
                LDM4(AH[mt], ra);
                LDM4(AL[mt], ra + TILE_SM);
            }
            #pragma unroll
            for (int p = 0; p < 2; p++) {
                uint32_t rb = st + 2 * TILE_SM + (wn * 32 + p * 16) * TPITCH + ko;
                LDM4(BH[p], rb);
                LDM4(BL[p], rb + TILE_SM);
            }
            #pragma unroll
            for (int mt = 0; mt < 2; mt++) {
                uint32_t HH[4], HL[4];
                #pragma unroll
                for (int i = 0; i < 4; i++) {
                    HH[i] = __byte_perm(AH[mt][i], AH[mt][i], 0x1032) ^ 0x80000000u;
                    HL[i] = __byte_perm(AL[mt][i], AL[mt][i], 0x1032) ^ 0x80000000u;
                }
                #pragma unroll
                for (int nt = 0; nt < 4; nt++) {
                    int p = nt >> 1, q = nt & 1;
                    uint32_t b0h = BH[p][q], b1h = BH[p][q + 2];
                    uint32_t b0l = BL[p][q], b1l = BL[p][q + 2];
                    MMA(accR[mt][nt], AH[mt], b0h, b1h);
                    MMA(accR[mt][nt], AH[mt], b0l, b1l);
                    MMA(accR[mt][nt], AL[mt], b0h, b1h);
                    MMA(accI[mt][nt], HH, b0h, b1h);
                    MMA(accI[mt][nt], HH, b0l, b1l);
                    MMA(accI[mt][nt], HL, b0h, b1h);
                }
            }
        }
        if (++buf >= NSTAGE) buf = 0;
    }

    // epilogue: direct stores + conjugate-transposed mirror
    float2* ob = out + ((size_t)b << 20);
    int rg = a0 + wm * 32 + (lane >> 2);
    int cg = c0 + wn * 32 + 2 * (lane & 3);
    #pragma unroll
    for (int mt = 0; mt < 2; mt++) {
        #pragma unroll
        for (int nt = 0; nt < 4; nt++) {
            int r = rg + mt * 16;
            int c = cg + nt * 8;
            float* R = accR[mt][nt];
            float* I = accI[mt][nt];
            *(float4*)&ob[((size_t)r << 10) + c]       = make_float4(R[0], I[0], R[1], I[1]);
            *(float4*)&ob[((size_t)(r + 8) << 10) + c] = make_float4(R[2], I[2], R[3], I[3]);
            if (bi != bj) {
                ob[((size_t)c << 10) + r]           = make_float2(R[0], -I[0]);
                ob[((size_t)(c + 1) << 10) + r]     = make_float2(R[1], -I[1]);
                ob[((size_t)c << 10) + r + 8]       = make_float2(R[2], -I[2]);
                ob[((size_t)(c + 1) << 10) + r + 8] = make_float2(R[3], -I[3]);
            }
        }
    }
}

// ---------------------------------------------------------------------------
extern "C" void kernel_launch(void* const* d_in, const int* in_sizes, int n_in,
                              void* d_out, int out_size) {
    const float* x = (const float*)d_in[0];
    const float* w = (const float*)d_in[1];
    (void)in_sizes; (void)n_in; (void)out_size;

    cudaFuncSetAttribute(kC, cudaFuncAttributeMaxDynamicSharedMemorySize, SMEM_KC);

    kprep<<<1, 64>>>(w);
    kA<<<BATCH * 256, 256>>>(x);
    kB<<<BATCH * 256, 256>>>();
    kC<<<BATCH * 36, 512, SMEM_KC>>>((float2*)d_out);
}